// round 2
// baseline (speedup 1.0000x reference)
#include <cuda_runtime.h>
#include <cuda_bf16.h>
#include <math.h>

#define Bsz 4
#define Tt 512
#define Cc 512
#define Hh 8
#define Dd 64
#define Ee 32
#define Ii 2048
#define Kk 2
#define Vv 32000
#define NTOK 2048           // B*T
#define NPAIR 4096          // NTOK*K

// ---------------- scratch (device globals; no allocation) ----------------
__device__ float g_h   [NTOK * Cc];
__device__ float g_x   [NTOK * Cc];
__device__ float g_q   [NTOK * Cc];
__device__ float g_k   [NTOK * Cc];
__device__ float g_v   [NTOK * Cc];
__device__ float g_ao  [NTOK * Cc];
__device__ float g_x2  [NTOK * Cc];
__device__ float g_rl  [NTOK * Ee];
__device__ float g_hid [NPAIR * Ii];   // gelu(w1) activations per selected pair
__device__ float g_po  [NPAIR * Cc];   // per-pair expert output
__device__ int   g_sel [NPAIR];
__device__ float g_rw  [NPAIR];
__device__ int   g_cnt [Ee];
__device__ int   g_bucket[Ee * NPAIR];

// ---------------- embedding ----------------
__global__ void embed_kernel(const int* __restrict__ ids, const float* __restrict__ emb,
                             float* __restrict__ H) {
    int t = blockIdx.x;
    int id = ids[t];
    const float* src = emb + (size_t)id * Cc;
    float* dst = H + (size_t)t * Cc;
    for (int c = threadIdx.x; c < Cc; c += blockDim.x) dst[c] = src[c];
}

// ---------------- layernorm (block per token) ----------------
__global__ void ln_kernel(const float* __restrict__ X, const float* __restrict__ g,
                          const float* __restrict__ b, float* __restrict__ Y) {
    int t = blockIdx.x, tid = threadIdx.x;
    const float* row = X + (size_t)t * Cc;
    __shared__ float red[128];
    float s = 0.f;
    for (int c = tid; c < Cc; c += 128) s += row[c];
    red[tid] = s; __syncthreads();
    for (int k = 64; k > 0; k >>= 1) { if (tid < k) red[tid] += red[tid + k]; __syncthreads(); }
    float mu = red[0] / Cc; __syncthreads();
    float s2 = 0.f;
    for (int c = tid; c < Cc; c += 128) { float d = row[c] - mu; s2 += d * d; }
    red[tid] = s2; __syncthreads();
    for (int k = 64; k > 0; k >>= 1) { if (tid < k) red[tid] += red[tid + k]; __syncthreads(); }
    float inv = rsqrtf(red[0] / Cc + 1e-5f);
    float* out = Y + (size_t)t * Cc;
    for (int c = tid; c < Cc; c += 128) out[c] = (row[c] - mu) * inv * g[c] + b[c];
}

// ---------------- generic tiled fp32 GEMM: C = A[MxK] @ B[KxN] (+R) ----------------
// 64x64 tile, BK=16, 128 threads, 8x4 per thread.
__global__ void gemm_kernel(const float* __restrict__ A, const float* __restrict__ B,
                            const float* __restrict__ R, float* __restrict__ C,
                            int M, int N, int Kd) {
    __shared__ float As[16][68];   // [k][m]
    __shared__ float Bs[16][68];   // [k][n]
    int tid = threadIdx.x;
    int tx = tid & 15;             // n-group (4 cols)
    int ty = tid >> 4;             // m-group (8 rows)
    int rowBase = blockIdx.y * 64;
    int colBase = blockIdx.x * 64;
    float acc[8][4];
    #pragma unroll
    for (int i = 0; i < 8; i++)
        #pragma unroll
        for (int j = 0; j < 4; j++) acc[i][j] = 0.f;

    int lkA = tid & 15, lm8 = tid >> 4;       // A loader
    int lnB = tid & 63, lkB = tid >> 6;       // B loader

    for (int k0 = 0; k0 < Kd; k0 += 16) {
        #pragma unroll
        for (int mi = 0; mi < 8; mi++) {
            int m = lm8 * 8 + mi;
            int gr = rowBase + m, gk = k0 + lkA;
            As[lkA][m] = (gr < M && gk < Kd) ? A[(size_t)gr * Kd + gk] : 0.f;
        }
        #pragma unroll
        for (int ki = 0; ki < 8; ki++) {
            int k = lkB * 8 + ki;
            int gk = k0 + k, gc = colBase + lnB;
            Bs[k][lnB] = (gk < Kd && gc < N) ? B[(size_t)gk * N + gc] : 0.f;
        }
        __syncthreads();
        #pragma unroll
        for (int k = 0; k < 16; k++) {
            float a[8], bb[4];
            #pragma unroll
            for (int i = 0; i < 8; i++) a[i] = As[k][ty * 8 + i];
            #pragma unroll
            for (int j = 0; j < 4; j++) bb[j] = Bs[k][tx * 4 + j];
            #pragma unroll
            for (int i = 0; i < 8; i++)
                #pragma unroll
                for (int j = 0; j < 4; j++) acc[i][j] = fmaf(a[i], bb[j], acc[i][j]);
        }
        __syncthreads();
    }
    #pragma unroll
    for (int i = 0; i < 8; i++) {
        int gr = rowBase + ty * 8 + i;
        if (gr >= M) continue;
        #pragma unroll
        for (int j = 0; j < 4; j++) {
            int gc = colBase + tx * 4 + j;
            if (gc >= N) continue;
            float val = acc[i][j];
            if (R) val += R[(size_t)gr * N + gc];
            C[(size_t)gr * N + gc] = val;
        }
    }
}

// ---------------- attention: one block per (b,h,q) ----------------
__global__ void attn_kernel(const float* __restrict__ Q, const float* __restrict__ Km,
                            const float* __restrict__ Vm, float* __restrict__ AO) {
    int r = blockIdx.x;
    int qpos = r % Tt;
    int hh = (r / Tt) % Hh;
    int bb = r / (Tt * Hh);
    int tid = threadIdx.x;
    __shared__ float qs[64];
    __shared__ float sc[Tt];
    __shared__ float red[128];
    const float* qrow = Q + ((size_t)(bb * Tt + qpos)) * Cc + hh * Dd;
    if (tid < 64) qs[tid] = qrow[tid] * 0.125f;   // 1/sqrt(64) folded in
    __syncthreads();
    float lmax = -1e30f;
    for (int j = tid; j <= qpos; j += 128) {
        const float* krow = Km + ((size_t)(bb * Tt + j)) * Cc + hh * Dd;
        float d = 0.f;
        #pragma unroll
        for (int dd = 0; dd < 64; dd += 4) {
            float4 k4 = *reinterpret_cast<const float4*>(krow + dd);
            d += qs[dd] * k4.x + qs[dd + 1] * k4.y + qs[dd + 2] * k4.z + qs[dd + 3] * k4.w;
        }
        sc[j] = d;
        lmax = fmaxf(lmax, d);
    }
    red[tid] = lmax; __syncthreads();
    for (int s = 64; s > 0; s >>= 1) { if (tid < s) red[tid] = fmaxf(red[tid], red[tid + s]); __syncthreads(); }
    float mx = red[0]; __syncthreads();
    float lsum = 0.f;
    for (int j = tid; j <= qpos; j += 128) { float p = __expf(sc[j] - mx); sc[j] = p; lsum += p; }
    red[tid] = lsum; __syncthreads();
    for (int s = 64; s > 0; s >>= 1) { if (tid < s) red[tid] += red[tid + s]; __syncthreads(); }
    float inv = 1.f / red[0]; __syncthreads();
    int dd = tid & 63, part = tid >> 6;
    float accv = 0.f;
    for (int j = part; j <= qpos; j += 2)
        accv = fmaf(sc[j], Vm[((size_t)(bb * Tt + j)) * Cc + hh * Dd + dd], accv);
    red[tid] = accv; __syncthreads();
    if (tid < 64)
        AO[((size_t)(bb * Tt + qpos)) * Cc + hh * Dd + tid] = (red[tid] + red[tid + 64]) * inv;
}

// ---------------- routing: top-2 + softmax + expert buckets ----------------
__global__ void zero_cnt_kernel() { if (threadIdx.x < Ee) g_cnt[threadIdx.x] = 0; }

__global__ void topk_kernel(const float* __restrict__ RL) {
    int t = blockIdx.x * blockDim.x + threadIdx.x;
    if (t >= NTOK) return;
    const float* r = RL + (size_t)t * Ee;
    int i1 = 0; float v1 = r[0];
    for (int e = 1; e < Ee; e++) if (r[e] > v1) { v1 = r[e]; i1 = e; }
    int i2 = -1; float v2 = -3.4e38f;
    for (int e = 0; e < Ee; e++) { if (e == i1) continue; if (r[e] > v2) { v2 = r[e]; i2 = e; } }
    float e1 = __expf(v1 - v1), e2 = __expf(v2 - v1);
    float inv = 1.f / (e1 + e2);
    g_sel[t * 2] = i1; g_sel[t * 2 + 1] = i2;
    g_rw[t * 2] = e1 * inv; g_rw[t * 2 + 1] = e2 * inv;
    int s1 = atomicAdd(&g_cnt[i1], 1); g_bucket[i1 * NPAIR + s1] = t * 2;
    int s2 = atomicAdd(&g_cnt[i2], 1); g_bucket[i2 * NPAIR + s2] = t * 2 + 1;
}

// ---------------- MoE GEMM1: hidden = gelu(x2 @ w1[e]), 16-token tiles ----------------
__global__ void moe_gemm1(const float* __restrict__ X2, const float* __restrict__ W1) {
    int e = blockIdx.z;
    int n = g_cnt[e];
    int t0 = blockIdx.y * 16;
    if (t0 >= n) return;
    int nt = min(16, n - t0);
    __shared__ float xs[16][Cc];
    __shared__ int ps[16];
    int tid = threadIdx.x;
    if (tid < 16) ps[tid] = (tid < nt) ? g_bucket[e * NPAIR + t0 + tid] : -1;
    __syncthreads();
    for (int idx = tid; idx < 16 * Cc; idx += 128) {
        int m = idx / Cc, c = idx % Cc;
        int p = ps[m];
        xs[m][c] = (p >= 0) ? X2[(size_t)(p >> 1) * Cc + c] : 0.f;
    }
    __syncthreads();
    int i = blockIdx.x * 128 + tid;
    float acc[16];
    #pragma unroll
    for (int m = 0; m < 16; m++) acc[m] = 0.f;
    const float* wp = W1 + (size_t)e * Cc * Ii + i;
    #pragma unroll 4
    for (int c = 0; c < Cc; c++) {
        float w = wp[(size_t)c * Ii];
        #pragma unroll
        for (int m = 0; m < 16; m++) acc[m] = fmaf(xs[m][c], w, acc[m]);
    }
    for (int m = 0; m < nt; m++) {
        float x = acc[m];
        float gv = 0.5f * x * (1.f + erff(x * 0.70710678118654752f));
        g_hid[(size_t)ps[m] * Ii + i] = gv;
    }
}

// ---------------- MoE GEMM2: pair_out = hidden @ w2[e] ----------------
__global__ void moe_gemm2(const float* __restrict__ W2) {
    int e = blockIdx.z;
    int n = g_cnt[e];
    int t0 = blockIdx.y * 16;
    if (t0 >= n) return;
    int nt = min(16, n - t0);
    __shared__ float hs[16][128];
    __shared__ int ps[16];
    int tid = threadIdx.x;
    if (tid < 16) ps[tid] = (tid < nt) ? g_bucket[e * NPAIR + t0 + tid] : -1;
    __syncthreads();
    int c = blockIdx.x * 128 + tid;
    float acc[16];
    #pragma unroll
    for (int m = 0; m < 16; m++) acc[m] = 0.f;
    for (int i0 = 0; i0 < Ii; i0 += 128) {
        __syncthreads();
        for (int idx = tid; idx < 16 * 128; idx += 128) {
            int m = idx >> 7, ii = idx & 127;
            int p = ps[m];
            hs[m][ii] = (p >= 0) ? g_hid[(size_t)p * Ii + i0 + ii] : 0.f;
        }
        __syncthreads();
        const float* wp = W2 + ((size_t)e * Ii + i0) * Cc + c;
        #pragma unroll 4
        for (int ii = 0; ii < 128; ii++) {
            float w = wp[(size_t)ii * Cc];
            #pragma unroll
            for (int m = 0; m < 16; m++) acc[m] = fmaf(hs[m][ii], w, acc[m]);
        }
    }
    for (int m = 0; m < nt; m++) g_po[(size_t)ps[m] * Cc + c] = acc[m];
}

// ---------------- scatter full_expert_outputs + combine ----------------
__global__ void feo_scatter(float* __restrict__ FEO) {
    int p = blockIdx.x;
    int t = p >> 1, e = g_sel[p];
    float* dst = FEO + ((size_t)t * Ee + e) * Cc;
    const float* src = g_po + (size_t)p * Cc;
    for (int c = threadIdx.x; c < Cc; c += 128) dst[c] = src[c];
}

__global__ void moe_combine() {
    int t = blockIdx.x;
    float w0 = g_rw[t * 2], w1r = g_rw[t * 2 + 1];
    float* hrow = g_h + (size_t)t * Cc;
    const float* p0 = g_po + (size_t)(t * 2) * Cc;
    const float* p1 = g_po + (size_t)(t * 2 + 1) * Cc;
    for (int c = threadIdx.x; c < Cc; c += 128)
        hrow[c] += w0 * p0[c] + w1r * p1[c];
}

// ---------------- launch ----------------
extern "C" void kernel_launch(void* const* d_in, const int* in_sizes, int n_in,
                              void* d_out, int out_size) {
    const int*   ids  = (const int*)d_in[0];
    const float* emb  = (const float*)d_in[1];
    const float* wq   = (const float*)d_in[2];
    const float* wk   = (const float*)d_in[3];
    const float* wv   = (const float*)d_in[4];
    const float* wo   = (const float*)d_in[5];
    const float* gate = (const float*)d_in[6];
    const float* w1   = (const float*)d_in[7];
    const float* w2   = (const float*)d_in[8];
    const float* g1   = (const float*)d_in[9];
    const float* b1   = (const float*)d_in[10];
    const float* g2   = (const float*)d_in[11];
    const float* b2   = (const float*)d_in[12];
    const float* lm   = (const float*)d_in[13];
    float* out = (float*)d_out;

    float *p_h, *p_x, *p_q, *p_k, *p_v, *p_ao, *p_x2, *p_rl;
    cudaGetSymbolAddress((void**)&p_h,  g_h);
    cudaGetSymbolAddress((void**)&p_x,  g_x);
    cudaGetSymbolAddress((void**)&p_q,  g_q);
    cudaGetSymbolAddress((void**)&p_k,  g_k);
    cudaGetSymbolAddress((void**)&p_v,  g_v);
    cudaGetSymbolAddress((void**)&p_ao, g_ao);
    cudaGetSymbolAddress((void**)&p_x2, g_x2);
    cudaGetSymbolAddress((void**)&p_rl, g_rl);

    const size_t L_LOG = (size_t)NTOK * Vv;            // 65,536,000
    const size_t L_FEO = (size_t)NTOK * Ee * Cc;       // 33,554,432
    const size_t L_RL  = (size_t)NTOK * Ee;            // 65,536
    const size_t L_X2  = (size_t)NTOK * Cc;            // 1,048,576
    const size_t OFF_FEO = L_LOG;
    const size_t OFF_RL  = OFF_FEO + L_FEO;
    const size_t OFF_X2  = OFF_RL + L_RL;
    bool full = (size_t)out_size >= OFF_X2 + L_X2;

    // 1. embedding
    embed_kernel<<<NTOK, 128>>>(ids, emb, p_h);
    // 2. LN1
    ln_kernel<<<NTOK, 128>>>(p_h, g1, b1, p_x);
    // 3. Q,K,V projections
    dim3 gproj(Cc / 64, NTOK / 64);
    gemm_kernel<<<gproj, 128>>>(p_x, wq, nullptr, p_q, NTOK, Cc, Cc);
    gemm_kernel<<<gproj, 128>>>(p_x, wk, nullptr, p_k, NTOK, Cc, Cc);
    gemm_kernel<<<gproj, 128>>>(p_x, wv, nullptr, p_v, NTOK, Cc, Cc);
    // 4. attention
    attn_kernel<<<Bsz * Hh * Tt, 128>>>(p_q, p_k, p_v, p_ao);
    // 5. output projection + residual (in-place into h)
    gemm_kernel<<<gproj, 128>>>(p_ao, wo, p_h, p_h, NTOK, Cc, Cc);
    // 6. LN2 -> x2
    ln_kernel<<<NTOK, 128>>>(p_h, g2, b2, p_x2);
    // 7. router logits
    gemm_kernel<<<dim3(1, NTOK / 64), 128>>>(p_x2, gate, nullptr, p_rl, NTOK, Ee, Cc);
    // 8. routing
    zero_cnt_kernel<<<1, 32>>>();
    topk_kernel<<<NTOK / 128, 128>>>(p_rl);
    // 9-10. MoE
    moe_gemm1<<<dim3(Ii / 128, NPAIR / 16, Ee), 128>>>(p_x2, w1);
    moe_gemm2<<<dim3(Cc / 128, NPAIR / 16, Ee), 128>>>(w2);
    // 11. full_expert_outputs: zero + scatter
    if (full) {
        cudaMemsetAsync(out + OFF_FEO, 0, L_FEO * sizeof(float));
        feo_scatter<<<NPAIR, 128>>>(out + OFF_FEO);
    }
    // 12. residual add of weighted expert outputs
    moe_combine<<<NTOK, 128>>>();
    // 13. lm_head -> logits (start of d_out)
    gemm_kernel<<<dim3(Vv / 64, NTOK / 64), 128>>>(p_h, lm, nullptr, out, NTOK, Vv, Cc);
    // 14. small outputs
    if (full) {
        cudaMemcpyAsync(out + OFF_RL, p_rl, L_RL * sizeof(float), cudaMemcpyDeviceToDevice);
        cudaMemcpyAsync(out + OFF_X2, p_x2, L_X2 * sizeof(float), cudaMemcpyDeviceToDevice);
    }
}

// round 4
// speedup vs baseline: 1.2176x; 1.2176x over previous
#include <cuda_runtime.h>
#include <cuda_bf16.h>
#include <math.h>
#include <stdint.h>

#define Bsz 4
#define Tt 512
#define Cc 512
#define Hh 8
#define Dd 64
#define Ee 32
#define Ii 2048
#define Kk 2
#define Vv 32000
#define NTOK 2048           // B*T
#define NPAIR 4096          // NTOK*K

// ---------------- scratch (device globals; no allocation) ----------------
__device__ float g_h   [NTOK * Cc];
__device__ float g_x   [NTOK * Cc];
__device__ float g_q   [NTOK * Cc];
__device__ float g_k   [NTOK * Cc];
__device__ float g_v   [NTOK * Cc];
__device__ float g_ao  [NTOK * Cc];
__device__ float g_x2  [NTOK * Cc];
__device__ float g_rl  [NTOK * Ee];
__device__ float g_hid [NPAIR * Ii];
__device__ float g_po  [NPAIR * Cc];
__device__ int   g_sel [NPAIR];
__device__ float g_rw  [NPAIR];
__device__ int   g_cnt [Ee];
__device__ int   g_bucket[Ee * NPAIR];

// ---------------- embedding ----------------
__global__ void embed_kernel(const int* __restrict__ ids, const float* __restrict__ emb,
                             float* __restrict__ H) {
    int t = blockIdx.x;
    int id = ids[t];
    const float* src = emb + (size_t)id * Cc;
    float* dst = H + (size_t)t * Cc;
    for (int c = threadIdx.x; c < Cc; c += blockDim.x) dst[c] = src[c];
}

// ---------------- layernorm (block per token) ----------------
__global__ void ln_kernel(const float* __restrict__ X, const float* __restrict__ g,
                          const float* __restrict__ b, float* __restrict__ Y) {
    int t = blockIdx.x, tid = threadIdx.x;
    const float* row = X + (size_t)t * Cc;
    __shared__ float red[128];
    float s = 0.f;
    for (int c = tid; c < Cc; c += 128) s += row[c];
    red[tid] = s; __syncthreads();
    for (int k = 64; k > 0; k >>= 1) { if (tid < k) red[tid] += red[tid + k]; __syncthreads(); }
    float mu = red[0] / Cc; __syncthreads();
    float s2 = 0.f;
    for (int c = tid; c < Cc; c += 128) { float d = row[c] - mu; s2 += d * d; }
    red[tid] = s2; __syncthreads();
    for (int k = 64; k > 0; k >>= 1) { if (tid < k) red[tid] += red[tid + k]; __syncthreads(); }
    float inv = rsqrtf(red[0] / Cc + 1e-5f);
    float* out = Y + (size_t)t * Cc;
    for (int c = tid; c < 128; c += 128) {}
    for (int c = tid; c < Cc; c += 128) out[c] = (row[c] - mu) * inv * g[c] + b[c];
}

// ---------------- tf32x3 tensor-core GEMM ----------------
// C = A[MxK] @ B[KxN] (+R). Requires M%128==0, N%128==0, K%32==0.
// 128x128 block tile, BK=32, 256 threads = 8 warps (2M x 4N), warp tile 64x32.
// Each fp32 operand split: hi = tf32(x), lo = tf32(x - hi); acc += hi*hi + lo*hi + hi*lo.

#define A_LD 36
#define B_LD 136
#define SMEM_A_ELEMS (128 * A_LD)
#define SMEM_B_ELEMS (32 * B_LD)
#define GEMM_SMEM_BYTES ((2 * SMEM_A_ELEMS + 2 * SMEM_B_ELEMS) * 4)

__device__ __forceinline__ uint32_t smem_u32(const void* p) {
    uint32_t a;
    asm("{ .reg .u64 t; cvta.to.shared.u64 t, %1; cvt.u32.u64 %0, t; }" : "=r"(a) : "l"(p));
    return a;
}
__device__ __forceinline__ void cp16(uint32_t dst, const void* src) {
    asm volatile("cp.async.cg.shared.global [%0], [%1], 16;" :: "r"(dst), "l"(src));
}
__device__ __forceinline__ void f2tf2(float x, uint32_t& hi, uint32_t& lo) {
    uint32_t h;
    asm("cvt.rna.tf32.f32 %0, %1;" : "=r"(h) : "f"(x));
    float r = x - __uint_as_float(h);
    uint32_t l;
    asm("cvt.rna.tf32.f32 %0, %1;" : "=r"(l) : "f"(r));
    hi = h; lo = l;
}
__device__ __forceinline__ void mma_tf32(float* d, const uint32_t* a, const uint32_t* b) {
    asm volatile(
        "mma.sync.aligned.m16n8k8.row.col.f32.tf32.tf32.f32 "
        "{%0,%1,%2,%3}, {%4,%5,%6,%7}, {%8,%9}, {%0,%1,%2,%3};"
        : "+f"(d[0]), "+f"(d[1]), "+f"(d[2]), "+f"(d[3])
        : "r"(a[0]), "r"(a[1]), "r"(a[2]), "r"(a[3]), "r"(b[0]), "r"(b[1]));
}

__global__ __launch_bounds__(256, 2)
void mma_gemm(const float* __restrict__ A, const float* __restrict__ B,
              const float* __restrict__ R, float* __restrict__ C,
              int M, int N, int K) {
    extern __shared__ float sm[];
    float* As = sm;                          // [2][128][A_LD]
    float* Bs = sm + 2 * SMEM_A_ELEMS;       // [2][32][B_LD]

    int tid = threadIdx.x;
    int lane = tid & 31;
    int warp = tid >> 5;
    int wm = warp & 1;
    int wn = warp >> 1;
    int rowBase = blockIdx.y * 128;
    int colBase = blockIdx.x * 128;

    float acc[4][4][4];
    #pragma unroll
    for (int mi = 0; mi < 4; mi++)
        #pragma unroll
        for (int ni = 0; ni < 4; ni++)
            #pragma unroll
            for (int r = 0; r < 4; r++) acc[mi][ni][r] = 0.f;

    int nIter = K >> 5;

    auto loadTile = [&](int it, int buf) {
        int k0 = it * 32;
        float* Ab = As + buf * SMEM_A_ELEMS;
        float* Bb = Bs + buf * SMEM_B_ELEMS;
        #pragma unroll
        for (int t = 0; t < 4; t++) {
            int id = tid + t * 256;
            int ar = id >> 3, ac4 = id & 7;
            cp16(smem_u32(Ab + ar * A_LD + ac4 * 4),
                 A + (size_t)(rowBase + ar) * K + k0 + ac4 * 4);
            int br = id >> 5, bc4 = id & 31;
            cp16(smem_u32(Bb + br * B_LD + bc4 * 4),
                 B + (size_t)(k0 + br) * N + colBase + bc4 * 4);
        }
    };

    loadTile(0, 0);
    asm volatile("cp.async.commit_group;");

    int rbase = wm * 64;
    int cbase = wn * 32;
    int lr = lane >> 2;
    int lc = lane & 3;

    for (int it = 0; it < nIter; it++) {
        int buf = it & 1;
        if (it + 1 < nIter) {
            loadTile(it + 1, buf ^ 1);
            asm volatile("cp.async.commit_group;");
            asm volatile("cp.async.wait_group 1;");
        } else {
            asm volatile("cp.async.wait_group 0;");
        }
        __syncthreads();

        const float* Ab = As + buf * SMEM_A_ELEMS;
        const float* Bb = Bs + buf * SMEM_B_ELEMS;
        #pragma unroll
        for (int ks = 0; ks < 4; ks++) {
            int kk = ks * 8;
            uint32_t bh[4][2], bl[4][2];
            #pragma unroll
            for (int ni = 0; ni < 4; ni++) {
                const float* bp = Bb + (kk + lc) * B_LD + cbase + ni * 8 + lr;
                f2tf2(bp[0], bh[ni][0], bl[ni][0]);
                f2tf2(bp[4 * B_LD], bh[ni][1], bl[ni][1]);
            }
            #pragma unroll
            for (int mi = 0; mi < 4; mi++) {
                const float* ap = Ab + (rbase + mi * 16 + lr) * A_LD + kk + lc;
                uint32_t ah[4], al[4];
                f2tf2(ap[0],              ah[0], al[0]);
                f2tf2(ap[8 * A_LD],       ah[1], al[1]);
                f2tf2(ap[4],              ah[2], al[2]);
                f2tf2(ap[8 * A_LD + 4],   ah[3], al[3]);
                #pragma unroll
                for (int ni = 0; ni < 4; ni++) {
                    mma_tf32(acc[mi][ni], ah, bh[ni]);
                    mma_tf32(acc[mi][ni], al, bh[ni]);
                    mma_tf32(acc[mi][ni], ah, bl[ni]);
                }
            }
        }
        __syncthreads();
    }

    // epilogue
    #pragma unroll
    for (int mi = 0; mi < 4; mi++) {
        int gr0 = rowBase + rbase + mi * 16 + lr;
        #pragma unroll
        for (int ni = 0; ni < 4; ni++) {
            int gc = colBase + cbase + ni * 8 + 2 * lc;
            float2 v0 = make_float2(acc[mi][ni][0], acc[mi][ni][1]);
            float2 v1 = make_float2(acc[mi][ni][2], acc[mi][ni][3]);
            if (R) {
                const float2 r0 = *reinterpret_cast<const float2*>(R + (size_t)gr0 * N + gc);
                const float2 r1 = *reinterpret_cast<const float2*>(R + (size_t)(gr0 + 8) * N + gc);
                v0.x += r0.x; v0.y += r0.y; v1.x += r1.x; v1.y += r1.y;
            }
            *reinterpret_cast<float2*>(C + (size_t)gr0 * N + gc) = v0;
            *reinterpret_cast<float2*>(C + (size_t)(gr0 + 8) * N + gc) = v1;
        }
    }
}

// ---------------- generic tiled fp32 GEMM (for router: N=32) ----------------
__global__ void gemm_kernel(const float* __restrict__ A, const float* __restrict__ B,
                            const float* __restrict__ R, float* __restrict__ C,
                            int M, int N, int Kd) {
    __shared__ float As[16][68];
    __shared__ float Bs[16][68];
    int tid = threadIdx.x;
    int tx = tid & 15;
    int ty = tid >> 4;
    int rowBase = blockIdx.y * 64;
    int colBase = blockIdx.x * 64;
    float acc[8][4];
    #pragma unroll
    for (int i = 0; i < 8; i++)
        #pragma unroll
        for (int j = 0; j < 4; j++) acc[i][j] = 0.f;

    int lkA = tid & 15, lm8 = tid >> 4;
    int lnB = tid & 63, lkB = tid >> 6;

    for (int k0 = 0; k0 < Kd; k0 += 16) {
        #pragma unroll
        for (int mi = 0; mi < 8; mi++) {
            int m = lm8 * 8 + mi;
            int gr = rowBase + m, gk = k0 + lkA;
            As[lkA][m] = (gr < M && gk < Kd) ? A[(size_t)gr * Kd + gk] : 0.f;
        }
        #pragma unroll
        for (int ki = 0; ki < 8; ki++) {
            int k = lkB * 8 + ki;
            int gk = k0 + k, gc = colBase + lnB;
            Bs[k][lnB] = (gk < Kd && gc < N) ? B[(size_t)gk * N + gc] : 0.f;
        }
        __syncthreads();
        #pragma unroll
        for (int k = 0; k < 16; k++) {
            float a[8], bb[4];
            #pragma unroll
            for (int i = 0; i < 8; i++) a[i] = As[k][ty * 8 + i];
            #pragma unroll
            for (int j = 0; j < 4; j++) bb[j] = Bs[k][tx * 4 + j];
            #pragma unroll
            for (int i = 0; i < 8; i++)
                #pragma unroll
                for (int j = 0; j < 4; j++) acc[i][j] = fmaf(a[i], bb[j], acc[i][j]);
        }
        __syncthreads();
    }
    #pragma unroll
    for (int i = 0; i < 8; i++) {
        int gr = rowBase + ty * 8 + i;
        if (gr >= M) continue;
        #pragma unroll
        for (int j = 0; j < 4; j++) {
            int gc = colBase + tx * 4 + j;
            if (gc >= N) continue;
            float val = acc[i][j];
            if (R) val += R[(size_t)gr * N + gc];
            C[(size_t)gr * N + gc] = val;
        }
    }
}

// ---------------- attention: one block per (b,h,q) ----------------
__global__ void attn_kernel(const float* __restrict__ Q, const float* __restrict__ Km,
                            const float* __restrict__ Vm, float* __restrict__ AO) {
    int r = blockIdx.x;
    int qpos = r % Tt;
    int hh = (r / Tt) % Hh;
    int bb = r / (Tt * Hh);
    int tid = threadIdx.x;
    __shared__ float qs[64];
    __shared__ float sc[Tt];
    __shared__ float red[128];
    const float* qrow = Q + ((size_t)(bb * Tt + qpos)) * Cc + hh * Dd;
    if (tid < 64) qs[tid] = qrow[tid] * 0.125f;
    __syncthreads();
    float lmax = -1e30f;
    for (int j = tid; j <= qpos; j += 128) {
        const float* krow = Km + ((size_t)(bb * Tt + j)) * Cc + hh * Dd;
        float d = 0.f;
        #pragma unroll
        for (int dd = 0; dd < 64; dd += 4) {
            float4 k4 = *reinterpret_cast<const float4*>(krow + dd);
            d += qs[dd] * k4.x + qs[dd + 1] * k4.y + qs[dd + 2] * k4.z + qs[dd + 3] * k4.w;
        }
        sc[j] = d;
        lmax = fmaxf(lmax, d);
    }
    red[tid] = lmax; __syncthreads();
    for (int s = 64; s > 0; s >>= 1) { if (tid < s) red[tid] = fmaxf(red[tid], red[tid + s]); __syncthreads(); }
    float mx = red[0]; __syncthreads();
    float lsum = 0.f;
    for (int j = tid; j <= qpos; j += 128) { float p = __expf(sc[j] - mx); sc[j] = p; lsum += p; }
    red[tid] = lsum; __syncthreads();
    for (int s = 64; s > 0; s >>= 1) { if (tid < s) red[tid] += red[tid + s]; __syncthreads(); }
    float inv = 1.f / red[0]; __syncthreads();
    int dd = tid & 63, part = tid >> 6;
    float accv = 0.f;
    for (int j = part; j <= qpos; j += 2)
        accv = fmaf(sc[j], Vm[((size_t)(bb * Tt + j)) * Cc + hh * Dd + dd], accv);
    red[tid] = accv; __syncthreads();
    if (tid < 64)
        AO[((size_t)(bb * Tt + qpos)) * Cc + hh * Dd + tid] = (red[tid] + red[tid + 64]) * inv;
}

// ---------------- routing ----------------
__global__ void zero_cnt_kernel() { if (threadIdx.x < Ee) g_cnt[threadIdx.x] = 0; }

__global__ void topk_kernel(const float* __restrict__ RL) {
    int t = blockIdx.x * blockDim.x + threadIdx.x;
    if (t >= NTOK) return;
    const float* r = RL + (size_t)t * Ee;
    int i1 = 0; float v1 = r[0];
    for (int e = 1; e < Ee; e++) if (r[e] > v1) { v1 = r[e]; i1 = e; }
    int i2 = -1; float v2 = -3.4e38f;
    for (int e = 0; e < Ee; e++) { if (e == i1) continue; if (r[e] > v2) { v2 = r[e]; i2 = e; } }
    float e1 = 1.f, e2 = __expf(v2 - v1);
    float inv = 1.f / (e1 + e2);
    g_sel[t * 2] = i1; g_sel[t * 2 + 1] = i2;
    g_rw[t * 2] = e1 * inv; g_rw[t * 2 + 1] = e2 * inv;
    int s1 = atomicAdd(&g_cnt[i1], 1); g_bucket[i1 * NPAIR + s1] = t * 2;
    int s2 = atomicAdd(&g_cnt[i2], 1); g_bucket[i2 * NPAIR + s2] = t * 2 + 1;
}

// ---------------- MoE GEMM1 ----------------
__global__ void moe_gemm1(const float* __restrict__ X2, const float* __restrict__ W1) {
    int e = blockIdx.z;
    int n = g_cnt[e];
    int t0 = blockIdx.y * 16;
    if (t0 >= n) return;
    int nt = min(16, n - t0);
    __shared__ float xs[16][Cc];
    __shared__ int ps[16];
    int tid = threadIdx.x;
    if (tid < 16) ps[tid] = (tid < nt) ? g_bucket[e * NPAIR + t0 + tid] : -1;
    __syncthreads();
    for (int idx = tid; idx < 16 * Cc; idx += 128) {
        int m = idx / Cc, c = idx % Cc;
        int p = ps[m];
        xs[m][c] = (p >= 0) ? X2[(size_t)(p >> 1) * Cc + c] : 0.f;
    }
    __syncthreads();
    int i = blockIdx.x * 128 + tid;
    float acc[16];
    #pragma unroll
    for (int m = 0; m < 16; m++) acc[m] = 0.f;
    const float* wp = W1 + (size_t)e * Cc * Ii + i;
    #pragma unroll 4
    for (int c = 0; c < Cc; c++) {
        float w = wp[(size_t)c * Ii];
        #pragma unroll
        for (int m = 0; m < 16; m++) acc[m] = fmaf(xs[m][c], w, acc[m]);
    }
    for (int m = 0; m < nt; m++) {
        float x = acc[m];
        float gv = 0.5f * x * (1.f + erff(x * 0.70710678118654752f));
        g_hid[(size_t)ps[m] * Ii + i] = gv;
    }
}

// ---------------- MoE GEMM2 ----------------
__global__ void moe_gemm2(const float* __restrict__ W2) {
    int e = blockIdx.z;
    int n = g_cnt[e];
    int t0 = blockIdx.y * 16;
    if (t0 >= n) return;
    int nt = min(16, n - t0);
    __shared__ float hs[16][128];
    __shared__ int ps[16];
    int tid = threadIdx.x;
    if (tid < 16) ps[tid] = (tid < nt) ? g_bucket[e * NPAIR + t0 + tid] : -1;
    __syncthreads();
    int c = blockIdx.x * 128 + tid;
    float acc[16];
    #pragma unroll
    for (int m = 0; m < 16; m++) acc[m] = 0.f;
    for (int i0 = 0; i0 < Ii; i0 += 128) {
        __syncthreads();
        for (int idx = tid; idx < 16 * 128; idx += 128) {
            int m = idx >> 7, ii = idx & 127;
            int p = ps[m];
            hs[m][ii] = (p >= 0) ? g_hid[(size_t)p * Ii + i0 + ii] : 0.f;
        }
        __syncthreads();
        const float* wp = W2 + ((size_t)e * Ii + i0) * Cc + c;
        #pragma unroll 4
        for (int ii = 0; ii < 128; ii++) {
            float w = wp[(size_t)ii * Cc];
            #pragma unroll
            for (int m = 0; m < 16; m++) acc[m] = fmaf(hs[m][ii], w, acc[m]);
        }
    }
    for (int m = 0; m < nt; m++) g_po[(size_t)ps[m] * Cc + c] = acc[m];
}

// ---------------- scatter + combine ----------------
__global__ void feo_scatter(float* __restrict__ FEO) {
    int p = blockIdx.x;
    int t = p >> 1, e = g_sel[p];
    float* dst = FEO + ((size_t)t * Ee + e) * Cc;
    const float* src = g_po + (size_t)p * Cc;
    for (int c = threadIdx.x; c < Cc; c += 128) dst[c] = src[c];
}

__global__ void moe_combine() {
    int t = blockIdx.x;
    float w0 = g_rw[t * 2], w1r = g_rw[t * 2 + 1];
    float* hrow = g_h + (size_t)t * Cc;
    const float* p0 = g_po + (size_t)(t * 2) * Cc;
    const float* p1 = g_po + (size_t)(t * 2 + 1) * Cc;
    for (int c = threadIdx.x; c < Cc; c += 128)
        hrow[c] += w0 * p0[c] + w1r * p1[c];
}

// ---------------- launch ----------------
extern "C" void kernel_launch(void* const* d_in, const int* in_sizes, int n_in,
                              void* d_out, int out_size) {
    const int*   ids  = (const int*)d_in[0];
    const float* emb  = (const float*)d_in[1];
    const float* wq   = (const float*)d_in[2];
    const float* wk   = (const float*)d_in[3];
    const float* wv   = (const float*)d_in[4];
    const float* wo   = (const float*)d_in[5];
    const float* gate = (const float*)d_in[6];
    const float* w1   = (const float*)d_in[7];
    const float* w2   = (const float*)d_in[8];
    const float* g1   = (const float*)d_in[9];
    const float* b1   = (const float*)d_in[10];
    const float* g2   = (const float*)d_in[11];
    const float* b2   = (const float*)d_in[12];
    const float* lm   = (const float*)d_in[13];
    float* out = (float*)d_out;

    float *p_h, *p_x, *p_q, *p_k, *p_v, *p_ao, *p_x2, *p_rl;
    cudaGetSymbolAddress((void**)&p_h,  g_h);
    cudaGetSymbolAddress((void**)&p_x,  g_x);
    cudaGetSymbolAddress((void**)&p_q,  g_q);
    cudaGetSymbolAddress((void**)&p_k,  g_k);
    cudaGetSymbolAddress((void**)&p_v,  g_v);
    cudaGetSymbolAddress((void**)&p_ao, g_ao);
    cudaGetSymbolAddress((void**)&p_x2, g_x2);
    cudaGetSymbolAddress((void**)&p_rl, g_rl);

    cudaFuncSetAttribute(mma_gemm, cudaFuncAttributeMaxDynamicSharedMemorySize,
                         GEMM_SMEM_BYTES);

    const size_t L_LOG = (size_t)NTOK * Vv;
    const size_t L_FEO = (size_t)NTOK * Ee * Cc;
    const size_t L_RL  = (size_t)NTOK * Ee;
    const size_t L_X2  = (size_t)NTOK * Cc;
    const size_t OFF_FEO = L_LOG;
    const size_t OFF_RL  = OFF_FEO + L_FEO;
    const size_t OFF_X2  = OFF_RL + L_RL;
    bool full = (size_t)out_size >= OFF_X2 + L_X2;

    embed_kernel<<<NTOK, 128>>>(ids, emb, p_h);
    ln_kernel<<<NTOK, 128>>>(p_h, g1, b1, p_x);

    dim3 gproj(Cc / 128, NTOK / 128);   // (4, 16)
    mma_gemm<<<gproj, 256, GEMM_SMEM_BYTES>>>(p_x, wq, nullptr, p_q, NTOK, Cc, Cc);
    mma_gemm<<<gproj, 256, GEMM_SMEM_BYTES>>>(p_x, wk, nullptr, p_k, NTOK, Cc, Cc);
    mma_gemm<<<gproj, 256, GEMM_SMEM_BYTES>>>(p_x, wv, nullptr, p_v, NTOK, Cc, Cc);

    attn_kernel<<<Bsz * Hh * Tt, 128>>>(p_q, p_k, p_v, p_ao);

    mma_gemm<<<gproj, 256, GEMM_SMEM_BYTES>>>(p_ao, wo, p_h, p_h, NTOK, Cc, Cc);

    ln_kernel<<<NTOK, 128>>>(p_h, g2, b2, p_x2);

    gemm_kernel<<<dim3(1, NTOK / 64), 128>>>(p_x2, gate, nullptr, p_rl, NTOK, Ee, Cc);

    zero_cnt_kernel<<<1, 32>>>();
    topk_kernel<<<NTOK / 128, 128>>>(p_rl);

    moe_gemm1<<<dim3(Ii / 128, NPAIR / 16, Ee), 128>>>(p_x2, w1);
    moe_gemm2<<<dim3(Cc / 128, NPAIR / 16, Ee), 128>>>(w2);

    if (full) {
        cudaMemsetAsync(out + OFF_FEO, 0, L_FEO * sizeof(float));
        feo_scatter<<<NPAIR, 128>>>(out + OFF_FEO);
    }
    moe_combine<<<NTOK, 128>>>();

    mma_gemm<<<dim3(Vv / 128, NTOK / 128), 256, GEMM_SMEM_BYTES>>>(p_h, lm, nullptr, out, NTOK, Vv, Cc);

    if (full) {
        cudaMemcpyAsync(out + OFF_RL, p_rl, L_RL * sizeof(float), cudaMemcpyDeviceToDevice);
        cudaMemcpyAsync(out + OFF_X2, p_x2, L_X2 * sizeof(float), cudaMemcpyDeviceToDevice);
    }
}

// round 5
// speedup vs baseline: 1.5669x; 1.2869x over previous
#include <cuda_runtime.h>
#include <cuda_bf16.h>
#include <math.h>
#include <stdint.h>

#define Bsz 4
#define Tt 512
#define Cc 512
#define Hh 8
#define Dd 64
#define Ee 32
#define Ii 2048
#define Kk 2
#define Vv 32000
#define NTOK 2048
#define NPAIR 4096

// ---------------- scratch ----------------
__device__ float g_h   [NTOK * Cc];
__device__ float g_x   [NTOK * Cc];
__device__ float g_q   [NTOK * Cc];
__device__ float g_k   [NTOK * Cc];
__device__ float g_v   [NTOK * Cc];
__device__ float g_ao  [NTOK * Cc];
__device__ float g_x2  [NTOK * Cc];
__device__ float g_rl  [NTOK * Ee];
__device__ float g_hid [NPAIR * Ii];
__device__ float g_po  [NPAIR * Cc];
__device__ int   g_sel [NPAIR];
__device__ float g_rw  [NPAIR];
__device__ int   g_cnt [Ee];
__device__ int   g_bucket[Ee * NPAIR];

// ---------------- embedding ----------------
__global__ void embed_kernel(const int* __restrict__ ids, const float* __restrict__ emb,
                             float* __restrict__ H) {
    int t = blockIdx.x;
    int id = ids[t];
    const float* src = emb + (size_t)id * Cc;
    float* dst = H + (size_t)t * Cc;
    for (int c = threadIdx.x; c < Cc; c += blockDim.x) dst[c] = src[c];
}

// ---------------- layernorm ----------------
__global__ void ln_kernel(const float* __restrict__ X, const float* __restrict__ g,
                          const float* __restrict__ b, float* __restrict__ Y) {
    int t = blockIdx.x, tid = threadIdx.x;
    const float* row = X + (size_t)t * Cc;
    __shared__ float red[128];
    float s = 0.f;
    for (int c = tid; c < Cc; c += 128) s += row[c];
    red[tid] = s; __syncthreads();
    for (int k = 64; k > 0; k >>= 1) { if (tid < k) red[tid] += red[tid + k]; __syncthreads(); }
    float mu = red[0] / Cc; __syncthreads();
    float s2 = 0.f;
    for (int c = tid; c < Cc; c += 128) { float d = row[c] - mu; s2 += d * d; }
    red[tid] = s2; __syncthreads();
    for (int k = 64; k > 0; k >>= 1) { if (tid < k) red[tid] += red[tid + k]; __syncthreads(); }
    float inv = rsqrtf(red[0] / Cc + 1e-5f);
    float* out = Y + (size_t)t * Cc;
    for (int c = tid; c < Cc; c += 128) out[c] = (row[c] - mu) * inv * g[c] + b[c];
}

// ---------------- mma helpers ----------------
__device__ __forceinline__ uint32_t smem_u32(const void* p) {
    uint32_t a;
    asm("{ .reg .u64 t; cvta.to.shared.u64 t, %1; cvt.u32.u64 %0, t; }" : "=r"(a) : "l"(p));
    return a;
}
__device__ __forceinline__ void cp16(uint32_t dst, const void* src) {
    asm volatile("cp.async.cg.shared.global [%0], [%1], 16;" :: "r"(dst), "l"(src));
}
__device__ __forceinline__ void f2tf2(float x, uint32_t& hi, uint32_t& lo) {
    uint32_t h;
    asm("cvt.rna.tf32.f32 %0, %1;" : "=r"(h) : "f"(x));
    float r = x - __uint_as_float(h);
    uint32_t l;
    asm("cvt.rna.tf32.f32 %0, %1;" : "=r"(l) : "f"(r));
    hi = h; lo = l;
}
__device__ __forceinline__ uint32_t f2tf(float f) {
    uint32_t u;
    asm("cvt.rna.tf32.f32 %0, %1;" : "=r"(u) : "f"(f));
    return u;
}
__device__ __forceinline__ void mma_tf32(float* d, const uint32_t* a, const uint32_t* b) {
    asm volatile(
        "mma.sync.aligned.m16n8k8.row.col.f32.tf32.tf32.f32 "
        "{%0,%1,%2,%3}, {%4,%5,%6,%7}, {%8,%9}, {%0,%1,%2,%3};"
        : "+f"(d[0]), "+f"(d[1]), "+f"(d[2]), "+f"(d[3])
        : "r"(a[0]), "r"(a[1]), "r"(a[2]), "r"(a[3]), "r"(b[0]), "r"(b[1]));
}

// ---------------- tf32(x3) tensor-core GEMM ----------------
// C = A[MxK] @ B[KxN] (+R). 128x128 tile, BK=32, 256 thr = 8 warps (2Mx4N).
// xtra=1: 3xTF32 compensation (near-fp32). xtra=0: single-pass tf32.
// blockIdx.z selects (B,C) among up to 3 pairs (fused QKV).
#define A_LD 36
#define B_LD 136
#define SMEM_A_ELEMS (128 * A_LD)
#define SMEM_B_ELEMS (32 * B_LD)
#define GEMM_SMEM_BYTES ((2 * SMEM_A_ELEMS + 2 * SMEM_B_ELEMS) * 4)

__global__ __launch_bounds__(256, 2)
void mma_gemm(const float* __restrict__ A,
              const float* __restrict__ B0, const float* __restrict__ B1,
              const float* __restrict__ B2,
              const float* __restrict__ R,
              float* __restrict__ C0, float* __restrict__ C1, float* __restrict__ C2,
              int M, int N, int K, int xtra) {
    extern __shared__ float sm[];
    float* As = sm;
    float* Bs = sm + 2 * SMEM_A_ELEMS;

    const float* B = (blockIdx.z == 0) ? B0 : ((blockIdx.z == 1) ? B1 : B2);
    float* C = (blockIdx.z == 0) ? C0 : ((blockIdx.z == 1) ? C1 : C2);

    int tid = threadIdx.x;
    int lane = tid & 31;
    int warp = tid >> 5;
    int wm = warp & 1;
    int wn = warp >> 1;
    int rowBase = blockIdx.y * 128;
    int colBase = blockIdx.x * 128;

    float acc[4][4][4];
    #pragma unroll
    for (int mi = 0; mi < 4; mi++)
        #pragma unroll
        for (int ni = 0; ni < 4; ni++)
            #pragma unroll
            for (int r = 0; r < 4; r++) acc[mi][ni][r] = 0.f;

    int nIter = K >> 5;

    auto loadTile = [&](int it, int buf) {
        int k0 = it * 32;
        float* Ab = As + buf * SMEM_A_ELEMS;
        float* Bb = Bs + buf * SMEM_B_ELEMS;
        #pragma unroll
        for (int t = 0; t < 4; t++) {
            int id = tid + t * 256;
            int ar = id >> 3, ac4 = id & 7;
            cp16(smem_u32(Ab + ar * A_LD + ac4 * 4),
                 A + (size_t)(rowBase + ar) * K + k0 + ac4 * 4);
            int br = id >> 5, bc4 = id & 31;
            cp16(smem_u32(Bb + br * B_LD + bc4 * 4),
                 B + (size_t)(k0 + br) * N + colBase + bc4 * 4);
        }
    };

    loadTile(0, 0);
    asm volatile("cp.async.commit_group;");

    int rbase = wm * 64;
    int cbase = wn * 32;
    int lr = lane >> 2;
    int lc = lane & 3;

    for (int it = 0; it < nIter; it++) {
        int buf = it & 1;
        if (it + 1 < nIter) {
            loadTile(it + 1, buf ^ 1);
            asm volatile("cp.async.commit_group;");
            asm volatile("cp.async.wait_group 1;");
        } else {
            asm volatile("cp.async.wait_group 0;");
        }
        __syncthreads();

        const float* Ab = As + buf * SMEM_A_ELEMS;
        const float* Bb = Bs + buf * SMEM_B_ELEMS;
        #pragma unroll
        for (int ks = 0; ks < 4; ks++) {
            int kk = ks * 8;
            uint32_t bh[4][2], bl[4][2];
            #pragma unroll
            for (int ni = 0; ni < 4; ni++) {
                const float* bp = Bb + (kk + lc) * B_LD + cbase + ni * 8 + lr;
                f2tf2(bp[0], bh[ni][0], bl[ni][0]);
                f2tf2(bp[4 * B_LD], bh[ni][1], bl[ni][1]);
            }
            #pragma unroll
            for (int mi = 0; mi < 4; mi++) {
                const float* ap = Ab + (rbase + mi * 16 + lr) * A_LD + kk + lc;
                uint32_t ah[4], al[4];
                f2tf2(ap[0],            ah[0], al[0]);
                f2tf2(ap[8 * A_LD],     ah[1], al[1]);
                f2tf2(ap[4],            ah[2], al[2]);
                f2tf2(ap[8 * A_LD + 4], ah[3], al[3]);
                #pragma unroll
                for (int ni = 0; ni < 4; ni++) {
                    mma_tf32(acc[mi][ni], ah, bh[ni]);
                    if (xtra) {
                        mma_tf32(acc[mi][ni], al, bh[ni]);
                        mma_tf32(acc[mi][ni], ah, bl[ni]);
                    }
                }
            }
        }
        __syncthreads();
    }

    #pragma unroll
    for (int mi = 0; mi < 4; mi++) {
        int gr0 = rowBase + rbase + mi * 16 + lr;
        #pragma unroll
        for (int ni = 0; ni < 4; ni++) {
            int gc = colBase + cbase + ni * 8 + 2 * lc;
            float2 v0 = make_float2(acc[mi][ni][0], acc[mi][ni][1]);
            float2 v1 = make_float2(acc[mi][ni][2], acc[mi][ni][3]);
            if (R) {
                const float2 r0 = *reinterpret_cast<const float2*>(R + (size_t)gr0 * N + gc);
                const float2 r1 = *reinterpret_cast<const float2*>(R + (size_t)(gr0 + 8) * N + gc);
                v0.x += r0.x; v0.y += r0.y; v1.x += r1.x; v1.y += r1.y;
            }
            *reinterpret_cast<float2*>(C + (size_t)gr0 * N + gc) = v0;
            *reinterpret_cast<float2*>(C + (size_t)(gr0 + 8) * N + gc) = v1;
        }
    }
}

// ---------------- MoE tensor-core GEMMs ----------------
// 16-token x 256-col tile, BK=32, 256 thr = 8 warps each owning 32 cols.
// Gathered A rows (clamped index; invalid rows only pollute unstored outputs).
#define MB_LD 264
#define MOE_A_ELEMS (16 * A_LD)
#define MOE_B_ELEMS (32 * MB_LD)
#define MOE_SMEM_BYTES ((2 * MOE_A_ELEMS + 2 * MOE_B_ELEMS) * 4 + 64 * 4)

__device__ __forceinline__ float gelu_f(float x) {
    return 0.5f * x * (1.f + erff(x * 0.70710678118654752f));
}

// which==1: hidden = gelu(gather(X2) @ W1[e]);  K=Cc, N=Ii, out g_hid (row=pair)
// which==2: po = gather(g_hid) @ W2[e];         K=Ii, N=Cc, out g_po
__global__ __launch_bounds__(256, 2)
void moe_mma(const float* __restrict__ Asrc, const float* __restrict__ W,
             int Kd, int Nd, int which) {
    int e = blockIdx.z;
    int n = g_cnt[e];
    int t0 = blockIdx.y * 16;
    if (t0 >= n) return;
    int nt = min(16, n - t0);

    extern __shared__ float sm[];
    float* As = sm;
    float* Bs = sm + 2 * MOE_A_ELEMS;
    int* ps = (int*)(Bs + 2 * MOE_B_ELEMS);
    int* prow = ps + 16;

    int tid = threadIdx.x;
    if (tid < 16) {
        int p = (tid < nt) ? g_bucket[e * NPAIR + t0 + tid] : -1;
        ps[tid] = p;
        int r = (p >= 0) ? p : 0;
        prow[tid] = (which == 1) ? (r >> 1) : r;
    }
    __syncthreads();

    const float* Bw = W + (size_t)e * Cc * Ii + blockIdx.x * 256;

    int lane = tid & 31;
    int warp = tid >> 5;
    int cbase = warp * 32;
    int lr = lane >> 2;
    int lc = lane & 3;

    float acc[4][4];
    #pragma unroll
    for (int ni = 0; ni < 4; ni++)
        #pragma unroll
        for (int r = 0; r < 4; r++) acc[ni][r] = 0.f;

    int nIter = Kd >> 5;

    auto loadTile = [&](int it, int buf) {
        int k0 = it * 32;
        float* Ab = As + buf * MOE_A_ELEMS;
        float* Bb = Bs + buf * MOE_B_ELEMS;
        if (tid < 128) {
            int ar = tid >> 3, ac4 = tid & 7;
            cp16(smem_u32(Ab + ar * A_LD + ac4 * 4),
                 Asrc + (size_t)prow[ar] * Kd + k0 + ac4 * 4);
        }
        #pragma unroll
        for (int t = 0; t < 8; t++) {
            int id = tid + t * 256;
            int br = id >> 6, bc4 = id & 63;
            cp16(smem_u32(Bb + br * MB_LD + bc4 * 4),
                 Bw + (size_t)(k0 + br) * Nd + bc4 * 4);
        }
    };

    loadTile(0, 0);
    asm volatile("cp.async.commit_group;");

    for (int it = 0; it < nIter; it++) {
        int buf = it & 1;
        if (it + 1 < nIter) {
            loadTile(it + 1, buf ^ 1);
            asm volatile("cp.async.commit_group;");
            asm volatile("cp.async.wait_group 1;");
        } else {
            asm volatile("cp.async.wait_group 0;");
        }
        __syncthreads();

        const float* Ab = As + buf * MOE_A_ELEMS;
        const float* Bb = Bs + buf * MOE_B_ELEMS;
        #pragma unroll
        for (int ks = 0; ks < 4; ks++) {
            int kk = ks * 8;
            const float* ap = Ab + lr * A_LD + kk + lc;
            uint32_t ah[4], al[4];
            f2tf2(ap[0],            ah[0], al[0]);
            f2tf2(ap[8 * A_LD],     ah[1], al[1]);
            f2tf2(ap[4],            ah[2], al[2]);
            f2tf2(ap[8 * A_LD + 4], ah[3], al[3]);
            #pragma unroll
            for (int ni = 0; ni < 4; ni++) {
                const float* bp = Bb + (kk + lc) * MB_LD + cbase + ni * 8 + lr;
                uint32_t bh[2], bl[2];
                f2tf2(bp[0], bh[0], bl[0]);
                f2tf2(bp[4 * MB_LD], bh[1], bl[1]);
                mma_tf32(acc[ni], ah, bh);
                mma_tf32(acc[ni], al, bh);
                mma_tf32(acc[ni], ah, bl);
            }
        }
        __syncthreads();
    }

    int colBase = blockIdx.x * 256 + cbase;
    #pragma unroll
    for (int ni = 0; ni < 4; ni++) {
        int gc = colBase + ni * 8 + 2 * lc;
        if (lr < nt) {
            if (which == 1) {
                float* o = g_hid + (size_t)ps[lr] * Ii + gc;
                o[0] = gelu_f(acc[ni][0]); o[1] = gelu_f(acc[ni][1]);
            } else {
                float* o = g_po + (size_t)ps[lr] * Cc + gc;
                o[0] = acc[ni][0]; o[1] = acc[ni][1];
            }
        }
        if (lr + 8 < nt) {
            if (which == 1) {
                float* o = g_hid + (size_t)ps[lr + 8] * Ii + gc;
                o[0] = gelu_f(acc[ni][2]); o[1] = gelu_f(acc[ni][3]);
            } else {
                float* o = g_po + (size_t)ps[lr + 8] * Cc + gc;
                o[0] = acc[ni][2]; o[1] = acc[ni][3];
            }
        }
    }
}

// ---------------- scalar GEMM (router: N=32) ----------------
__global__ void gemm_kernel(const float* __restrict__ A, const float* __restrict__ B,
                            const float* __restrict__ R, float* __restrict__ C,
                            int M, int N, int Kd) {
    __shared__ float As2[16][68];
    __shared__ float Bs2[16][68];
    int tid = threadIdx.x;
    int tx = tid & 15;
    int ty = tid >> 4;
    int rowBase = blockIdx.y * 64;
    int colBase = blockIdx.x * 64;
    float acc[8][4];
    #pragma unroll
    for (int i = 0; i < 8; i++)
        #pragma unroll
        for (int j = 0; j < 4; j++) acc[i][j] = 0.f;

    int lkA = tid & 15, lm8 = tid >> 4;
    int lnB = tid & 63, lkB = tid >> 6;

    for (int k0 = 0; k0 < Kd; k0 += 16) {
        #pragma unroll
        for (int mi = 0; mi < 8; mi++) {
            int m = lm8 * 8 + mi;
            int gr = rowBase + m, gk = k0 + lkA;
            As2[lkA][m] = (gr < M && gk < Kd) ? A[(size_t)gr * Kd + gk] : 0.f;
        }
        #pragma unroll
        for (int ki = 0; ki < 8; ki++) {
            int k = lkB * 8 + ki;
            int gk = k0 + k, gc = colBase + lnB;
            Bs2[k][lnB] = (gk < Kd && gc < N) ? B[(size_t)gk * N + gc] : 0.f;
        }
        __syncthreads();
        #pragma unroll
        for (int k = 0; k < 16; k++) {
            float a[8], bb[4];
            #pragma unroll
            for (int i = 0; i < 8; i++) a[i] = As2[k][ty * 8 + i];
            #pragma unroll
            for (int j = 0; j < 4; j++) bb[j] = Bs2[k][tx * 4 + j];
            #pragma unroll
            for (int i = 0; i < 8; i++)
                #pragma unroll
                for (int j = 0; j < 4; j++) acc[i][j] = fmaf(a[i], bb[j], acc[i][j]);
        }
        __syncthreads();
    }
    #pragma unroll
    for (int i = 0; i < 8; i++) {
        int gr = rowBase + ty * 8 + i;
        if (gr >= M) continue;
        #pragma unroll
        for (int j = 0; j < 4; j++) {
            int gc = colBase + tx * 4 + j;
            if (gc >= N) continue;
            float val = acc[i][j];
            if (R) val += R[(size_t)gr * N + gc];
            C[(size_t)gr * N + gc] = val;
        }
    }
}

// ---------------- attention ----------------
__global__ void attn_kernel(const float* __restrict__ Q, const float* __restrict__ Km,
                            const float* __restrict__ Vm, float* __restrict__ AO) {
    int r = blockIdx.x;
    int qpos = r % Tt;
    int hh = (r / Tt) % Hh;
    int bb = r / (Tt * Hh);
    int tid = threadIdx.x;
    __shared__ float qs[64];
    __shared__ float sc[Tt];
    __shared__ float red[128];
    const float* qrow = Q + ((size_t)(bb * Tt + qpos)) * Cc + hh * Dd;
    if (tid < 64) qs[tid] = qrow[tid] * 0.125f;
    __syncthreads();
    float lmax = -1e30f;
    for (int j = tid; j <= qpos; j += 128) {
        const float* krow = Km + ((size_t)(bb * Tt + j)) * Cc + hh * Dd;
        float d = 0.f;
        #pragma unroll
        for (int dd = 0; dd < 64; dd += 4) {
            float4 k4 = *reinterpret_cast<const float4*>(krow + dd);
            d += qs[dd] * k4.x + qs[dd + 1] * k4.y + qs[dd + 2] * k4.z + qs[dd + 3] * k4.w;
        }
        sc[j] = d;
        lmax = fmaxf(lmax, d);
    }
    red[tid] = lmax; __syncthreads();
    for (int s = 64; s > 0; s >>= 1) { if (tid < s) red[tid] = fmaxf(red[tid], red[tid + s]); __syncthreads(); }
    float mx = red[0]; __syncthreads();
    float lsum = 0.f;
    for (int j = tid; j <= qpos; j += 128) { float p = __expf(sc[j] - mx); sc[j] = p; lsum += p; }
    red[tid] = lsum; __syncthreads();
    for (int s = 64; s > 0; s >>= 1) { if (tid < s) red[tid] += red[tid + s]; __syncthreads(); }
    float inv = 1.f / red[0]; __syncthreads();
    int dd = tid & 63, part = tid >> 6;
    float accv = 0.f;
    for (int j = part; j <= qpos; j += 2)
        accv = fmaf(sc[j], Vm[((size_t)(bb * Tt + j)) * Cc + hh * Dd + dd], accv);
    red[tid] = accv; __syncthreads();
    if (tid < 64)
        AO[((size_t)(bb * Tt + qpos)) * Cc + hh * Dd + tid] = (red[tid] + red[tid + 64]) * inv;
}

// ---------------- routing ----------------
__global__ void zero_cnt_kernel() { if (threadIdx.x < Ee) g_cnt[threadIdx.x] = 0; }

__global__ void topk_kernel(const float* __restrict__ RL) {
    int t = blockIdx.x * blockDim.x + threadIdx.x;
    if (t >= NTOK) return;
    const float* r = RL + (size_t)t * Ee;
    int i1 = 0; float v1 = r[0];
    for (int e = 1; e < Ee; e++) if (r[e] > v1) { v1 = r[e]; i1 = e; }
    int i2 = -1; float v2 = -3.4e38f;
    for (int e = 0; e < Ee; e++) { if (e == i1) continue; if (r[e] > v2) { v2 = r[e]; i2 = e; } }
    float e1 = 1.f, e2 = __expf(v2 - v1);
    float inv = 1.f / (e1 + e2);
    g_sel[t * 2] = i1; g_sel[t * 2 + 1] = i2;
    g_rw[t * 2] = e1 * inv; g_rw[t * 2 + 1] = e2 * inv;
    int s1 = atomicAdd(&g_cnt[i1], 1); g_bucket[i1 * NPAIR + s1] = t * 2;
    int s2 = atomicAdd(&g_cnt[i2], 1); g_bucket[i2 * NPAIR + s2] = t * 2 + 1;
}

// ---------------- scatter + combine ----------------
__global__ void feo_scatter(float* __restrict__ FEO) {
    int p = blockIdx.x;
    int t = p >> 1, e = g_sel[p];
    float* dst = FEO + ((size_t)t * Ee + e) * Cc;
    const float* src = g_po + (size_t)p * Cc;
    for (int c = threadIdx.x; c < Cc; c += 128) dst[c] = src[c];
}

__global__ void moe_combine() {
    int t = blockIdx.x;
    float w0 = g_rw[t * 2], w1r = g_rw[t * 2 + 1];
    float* hrow = g_h + (size_t)t * Cc;
    const float* p0 = g_po + (size_t)(t * 2) * Cc;
    const float* p1 = g_po + (size_t)(t * 2 + 1) * Cc;
    for (int c = threadIdx.x; c < Cc; c += 128)
        hrow[c] += w0 * p0[c] + w1r * p1[c];
}

// ---------------- launch ----------------
extern "C" void kernel_launch(void* const* d_in, const int* in_sizes, int n_in,
                              void* d_out, int out_size) {
    const int*   ids  = (const int*)d_in[0];
    const float* emb  = (const float*)d_in[1];
    const float* wq   = (const float*)d_in[2];
    const float* wk   = (const float*)d_in[3];
    const float* wv   = (const float*)d_in[4];
    const float* wo   = (const float*)d_in[5];
    const float* gate = (const float*)d_in[6];
    const float* w1   = (const float*)d_in[7];
    const float* w2   = (const float*)d_in[8];
    const float* g1   = (const float*)d_in[9];
    const float* b1   = (const float*)d_in[10];
    const float* g2   = (const float*)d_in[11];
    const float* b2   = (const float*)d_in[12];
    const float* lm   = (const float*)d_in[13];
    float* out = (float*)d_out;

    float *p_h, *p_x, *p_q, *p_k, *p_v, *p_ao, *p_x2, *p_rl, *p_hid;
    cudaGetSymbolAddress((void**)&p_h,  g_h);
    cudaGetSymbolAddress((void**)&p_x,  g_x);
    cudaGetSymbolAddress((void**)&p_q,  g_q);
    cudaGetSymbolAddress((void**)&p_k,  g_k);
    cudaGetSymbolAddress((void**)&p_v,  g_v);
    cudaGetSymbolAddress((void**)&p_ao, g_ao);
    cudaGetSymbolAddress((void**)&p_x2, g_x2);
    cudaGetSymbolAddress((void**)&p_rl, g_rl);
    cudaGetSymbolAddress((void**)&p_hid, g_hid);

    cudaFuncSetAttribute(mma_gemm, cudaFuncAttributeMaxDynamicSharedMemorySize,
                         GEMM_SMEM_BYTES);
    cudaFuncSetAttribute(moe_mma, cudaFuncAttributeMaxDynamicSharedMemorySize,
                         MOE_SMEM_BYTES);

    const size_t L_LOG = (size_t)NTOK * Vv;
    const size_t L_FEO = (size_t)NTOK * Ee * Cc;
    const size_t L_RL  = (size_t)NTOK * Ee;
    const size_t L_X2  = (size_t)NTOK * Cc;
    const size_t OFF_FEO = L_LOG;
    const size_t OFF_RL  = OFF_FEO + L_FEO;
    const size_t OFF_X2  = OFF_RL + L_RL;
    bool full = (size_t)out_size >= OFF_X2 + L_X2;

    embed_kernel<<<NTOK, 128>>>(ids, emb, p_h);
    ln_kernel<<<NTOK, 128>>>(p_h, g1, b1, p_x);

    // fused Q,K,V projections (grid.z = 3)
    mma_gemm<<<dim3(Cc / 128, NTOK / 128, 3), 256, GEMM_SMEM_BYTES>>>(
        p_x, wq, wk, wv, nullptr, p_q, p_k, p_v, NTOK, Cc, Cc, 1);

    attn_kernel<<<Bsz * Hh * Tt, 128>>>(p_q, p_k, p_v, p_ao);

    mma_gemm<<<dim3(Cc / 128, NTOK / 128, 1), 256, GEMM_SMEM_BYTES>>>(
        p_ao, wo, wo, wo, p_h, p_h, p_h, p_h, NTOK, Cc, Cc, 1);

    ln_kernel<<<NTOK, 128>>>(p_h, g2, b2, p_x2);

    gemm_kernel<<<dim3(1, NTOK / 64), 128>>>(p_x2, gate, nullptr, p_rl, NTOK, Ee, Cc);

    zero_cnt_kernel<<<1, 32>>>();
    topk_kernel<<<NTOK / 128, 128>>>(p_rl);

    // MoE via tensor cores (tf32x3)
    moe_mma<<<dim3(Ii / 256, NPAIR / 16, Ee), 256, MOE_SMEM_BYTES>>>(
        p_x2, w1, Cc, Ii, 1);
    moe_mma<<<dim3(Cc / 256, NPAIR / 16, Ee), 256, MOE_SMEM_BYTES>>>(
        p_hid, w2, Ii, Cc, 2);

    if (full) {
        cudaMemsetAsync(out + OFF_FEO, 0, L_FEO * sizeof(float));
        feo_scatter<<<NPAIR, 128>>>(out + OFF_FEO);
    }
    moe_combine<<<NTOK, 128>>>();

    // lm_head: single-pass tf32 (final layer; no error compounding)
    mma_gemm<<<dim3(Vv / 128, NTOK / 128, 1), 256, GEMM_SMEM_BYTES>>>(
        p_h, lm, lm, lm, nullptr, out, out, out, NTOK, Vv, Cc, 0);

    if (full) {
        cudaMemcpyAsync(out + OFF_RL, p_rl, L_RL * sizeof(float), cudaMemcpyDeviceToDevice);
        cudaMemcpyAsync(out + OFF_X2, p_x2, L_X2 * sizeof(float), cudaMemcpyDeviceToDevice);
    }
}

// round 6
// speedup vs baseline: 2.5294x; 1.6143x over previous
#include <cuda_runtime.h>
#include <cuda_bf16.h>
#include <math.h>
#include <stdint.h>

#define Bsz 4
#define Tt 512
#define Cc 512
#define Hh 8
#define Dd 64
#define Ee 32
#define Ii 2048
#define Kk 2
#define Vv 32000
#define NTOK 2048
#define NPAIR 4096

// ---------------- scratch ----------------
__device__ float g_h   [NTOK * Cc];
__device__ float g_x   [NTOK * Cc];
__device__ float g_q   [NTOK * Cc];
__device__ float g_k   [NTOK * Cc];
__device__ float g_v   [NTOK * Cc];
__device__ float g_ao  [NTOK * Cc];
__device__ float g_x2  [NTOK * Cc];
__device__ float g_rl  [NTOK * Ee];
__device__ float g_hid [NPAIR * Ii];
__device__ float g_po  [NPAIR * Cc];
__device__ int   g_sel [NPAIR];
__device__ float g_rw  [NPAIR];
__device__ int   g_cnt [Ee];
__device__ int   g_bucket[Ee * NPAIR];

// ---------------- embedding ----------------
__global__ void embed_kernel(const int* __restrict__ ids, const float* __restrict__ emb,
                             float* __restrict__ H) {
    int t = blockIdx.x;
    int id = ids[t];
    const float* src = emb + (size_t)id * Cc;
    float* dst = H + (size_t)t * Cc;
    for (int c = threadIdx.x; c < Cc; c += blockDim.x) dst[c] = src[c];
}

// ---------------- layernorm ----------------
__global__ void ln_kernel(const float* __restrict__ X, const float* __restrict__ g,
                          const float* __restrict__ b, float* __restrict__ Y) {
    int t = blockIdx.x, tid = threadIdx.x;
    const float* row = X + (size_t)t * Cc;
    __shared__ float red[128];
    float s = 0.f;
    for (int c = tid; c < Cc; c += 128) s += row[c];
    red[tid] = s; __syncthreads();
    for (int k = 64; k > 0; k >>= 1) { if (tid < k) red[tid] += red[tid + k]; __syncthreads(); }
    float mu = red[0] / Cc; __syncthreads();
    float s2 = 0.f;
    for (int c = tid; c < Cc; c += 128) { float d = row[c] - mu; s2 += d * d; }
    red[tid] = s2; __syncthreads();
    for (int k = 64; k > 0; k >>= 1) { if (tid < k) red[tid] += red[tid + k]; __syncthreads(); }
    float inv = rsqrtf(red[0] / Cc + 1e-5f);
    float* out = Y + (size_t)t * Cc;
    for (int c = tid; c < Cc; c += 128) out[c] = (row[c] - mu) * inv * g[c] + b[c];
}

// ---------------- mma helpers ----------------
__device__ __forceinline__ uint32_t smem_u32(const void* p) {
    uint32_t a;
    asm("{ .reg .u64 t; cvta.to.shared.u64 t, %1; cvt.u32.u64 %0, t; }" : "=r"(a) : "l"(p));
    return a;
}
__device__ __forceinline__ void cp16(uint32_t dst, const void* src) {
    asm volatile("cp.async.cg.shared.global [%0], [%1], 16;" :: "r"(dst), "l"(src));
}
__device__ __forceinline__ void f2tf2(float x, uint32_t& hi, uint32_t& lo) {
    uint32_t h;
    asm("cvt.rna.tf32.f32 %0, %1;" : "=r"(h) : "f"(x));
    float r = x - __uint_as_float(h);
    uint32_t l;
    asm("cvt.rna.tf32.f32 %0, %1;" : "=r"(l) : "f"(r));
    hi = h; lo = l;
}
__device__ __forceinline__ uint32_t f2tf(float f) {
    uint32_t u;
    asm("cvt.rna.tf32.f32 %0, %1;" : "=r"(u) : "f"(f));
    return u;
}
__device__ __forceinline__ void mma_tf32(float* d, const uint32_t* a, const uint32_t* b) {
    asm volatile(
        "mma.sync.aligned.m16n8k8.row.col.f32.tf32.tf32.f32 "
        "{%0,%1,%2,%3}, {%4,%5,%6,%7}, {%8,%9}, {%0,%1,%2,%3};"
        : "+f"(d[0]), "+f"(d[1]), "+f"(d[2]), "+f"(d[3])
        : "r"(a[0]), "r"(a[1]), "r"(a[2]), "r"(a[3]), "r"(b[0]), "r"(b[1]));
}

// ---------------- tf32(x3) tensor-core GEMM ----------------
#define A_LD 36
#define B_LD 136
#define SMEM_A_ELEMS (128 * A_LD)
#define SMEM_B_ELEMS (32 * B_LD)
#define GEMM_SMEM_BYTES ((2 * SMEM_A_ELEMS + 2 * SMEM_B_ELEMS) * 4)

template<int XTRA>
__global__ __launch_bounds__(256, 2)
void mma_gemm(const float* __restrict__ A,
              const float* __restrict__ B0, const float* __restrict__ B1,
              const float* __restrict__ B2,
              const float* __restrict__ R,
              float* __restrict__ C0, float* __restrict__ C1, float* __restrict__ C2,
              int M, int N, int K) {
    extern __shared__ float sm[];
    float* As = sm;
    float* Bs = sm + 2 * SMEM_A_ELEMS;

    const float* B = (blockIdx.z == 0) ? B0 : ((blockIdx.z == 1) ? B1 : B2);
    float* C = (blockIdx.z == 0) ? C0 : ((blockIdx.z == 1) ? C1 : C2);

    int tid = threadIdx.x;
    int lane = tid & 31;
    int warp = tid >> 5;
    int wm = warp & 1;
    int wn = warp >> 1;
    int rowBase = blockIdx.y * 128;
    int colBase = blockIdx.x * 128;

    float acc[4][4][4];
    #pragma unroll
    for (int mi = 0; mi < 4; mi++)
        #pragma unroll
        for (int ni = 0; ni < 4; ni++)
            #pragma unroll
            for (int r = 0; r < 4; r++) acc[mi][ni][r] = 0.f;

    int nIter = K >> 5;

    auto loadTile = [&](int it, int buf) {
        int k0 = it * 32;
        float* Ab = As + buf * SMEM_A_ELEMS;
        float* Bb = Bs + buf * SMEM_B_ELEMS;
        #pragma unroll
        for (int t = 0; t < 4; t++) {
            int id = tid + t * 256;
            int ar = id >> 3, ac4 = id & 7;
            cp16(smem_u32(Ab + ar * A_LD + ac4 * 4),
                 A + (size_t)(rowBase + ar) * K + k0 + ac4 * 4);
            int br = id >> 5, bc4 = id & 31;
            cp16(smem_u32(Bb + br * B_LD + bc4 * 4),
                 B + (size_t)(k0 + br) * N + colBase + bc4 * 4);
        }
    };

    loadTile(0, 0);
    asm volatile("cp.async.commit_group;");

    int rbase = wm * 64;
    int cbase = wn * 32;
    int lr = lane >> 2;
    int lc = lane & 3;

    for (int it = 0; it < nIter; it++) {
        int buf = it & 1;
        if (it + 1 < nIter) {
            loadTile(it + 1, buf ^ 1);
            asm volatile("cp.async.commit_group;");
            asm volatile("cp.async.wait_group 1;");
        } else {
            asm volatile("cp.async.wait_group 0;");
        }
        __syncthreads();

        const float* Ab = As + buf * SMEM_A_ELEMS;
        const float* Bb = Bs + buf * SMEM_B_ELEMS;
        #pragma unroll
        for (int ks = 0; ks < 4; ks++) {
            int kk = ks * 8;
            uint32_t bh[4][2], bl[4][2];
            #pragma unroll
            for (int ni = 0; ni < 4; ni++) {
                const float* bp = Bb + (kk + lc) * B_LD + cbase + ni * 8 + lr;
                if (XTRA) {
                    f2tf2(bp[0], bh[ni][0], bl[ni][0]);
                    f2tf2(bp[4 * B_LD], bh[ni][1], bl[ni][1]);
                } else {
                    bh[ni][0] = f2tf(bp[0]);
                    bh[ni][1] = f2tf(bp[4 * B_LD]);
                }
            }
            #pragma unroll
            for (int mi = 0; mi < 4; mi++) {
                const float* ap = Ab + (rbase + mi * 16 + lr) * A_LD + kk + lc;
                uint32_t ah[4], al[4];
                if (XTRA) {
                    f2tf2(ap[0],            ah[0], al[0]);
                    f2tf2(ap[8 * A_LD],     ah[1], al[1]);
                    f2tf2(ap[4],            ah[2], al[2]);
                    f2tf2(ap[8 * A_LD + 4], ah[3], al[3]);
                } else {
                    ah[0] = f2tf(ap[0]);
                    ah[1] = f2tf(ap[8 * A_LD]);
                    ah[2] = f2tf(ap[4]);
                    ah[3] = f2tf(ap[8 * A_LD + 4]);
                }
                #pragma unroll
                for (int ni = 0; ni < 4; ni++) {
                    mma_tf32(acc[mi][ni], ah, bh[ni]);
                    if (XTRA) {
                        mma_tf32(acc[mi][ni], al, bh[ni]);
                        mma_tf32(acc[mi][ni], ah, bl[ni]);
                    }
                }
            }
        }
        __syncthreads();
    }

    #pragma unroll
    for (int mi = 0; mi < 4; mi++) {
        int gr0 = rowBase + rbase + mi * 16 + lr;
        #pragma unroll
        for (int ni = 0; ni < 4; ni++) {
            int gc = colBase + cbase + ni * 8 + 2 * lc;
            float2 v0 = make_float2(acc[mi][ni][0], acc[mi][ni][1]);
            float2 v1 = make_float2(acc[mi][ni][2], acc[mi][ni][3]);
            if (R) {
                const float2 r0 = *reinterpret_cast<const float2*>(R + (size_t)gr0 * N + gc);
                const float2 r1 = *reinterpret_cast<const float2*>(R + (size_t)(gr0 + 8) * N + gc);
                v0.x += r0.x; v0.y += r0.y; v1.x += r1.x; v1.y += r1.y;
            }
            *reinterpret_cast<float2*>(C + (size_t)gr0 * N + gc) = v0;
            *reinterpret_cast<float2*>(C + (size_t)(gr0 + 8) * N + gc) = v1;
        }
    }
}

// ---------------- MoE tensor-core GEMMs (64-token x 128-col tiles) ----------------
#define MOE_M 64
#define MOE_A_ELEMS (MOE_M * A_LD)
#define MOE_B_ELEMS (32 * B_LD)
#define MOE_SMEM_BYTES ((2 * MOE_A_ELEMS + 2 * MOE_B_ELEMS) * 4 + 2 * MOE_M * 4)

__device__ __forceinline__ float gelu_f(float x) {
    return 0.5f * x * (1.f + erff(x * 0.70710678118654752f));
}

// which==1: hidden = gelu(gather(X2) @ W1[e]);  K=Cc, N=Ii
// which==2: po = gather(g_hid) @ W2[e];          K=Ii, N=Cc
__global__ __launch_bounds__(256, 2)
void moe_mma(const float* __restrict__ Asrc, const float* __restrict__ W,
             int Kd, int Nd, int which) {
    int e = blockIdx.z;
    int n = g_cnt[e];
    int t0 = blockIdx.y * MOE_M;
    if (t0 >= n) return;
    int nt = min(MOE_M, n - t0);

    extern __shared__ float sm[];
    float* As = sm;
    float* Bs = sm + 2 * MOE_A_ELEMS;
    int* ps = (int*)(Bs + 2 * MOE_B_ELEMS);
    int* prow = ps + MOE_M;

    int tid = threadIdx.x;
    if (tid < MOE_M) {
        int p = (tid < nt) ? g_bucket[e * NPAIR + t0 + tid] : -1;
        ps[tid] = p;
        int r = (p >= 0) ? p : 0;
        prow[tid] = (which == 1) ? (r >> 1) : r;
    }
    __syncthreads();

    const float* Bw = W + (size_t)e * Cc * Ii + blockIdx.x * 128;

    int lane = tid & 31;
    int warp = tid >> 5;
    int wm = warp >> 1;            // 0..3 (16-row slab)
    int wn = warp & 1;             // 0..1 (64-col slab)
    int lr = lane >> 2;
    int lc = lane & 3;

    float acc[8][4];
    #pragma unroll
    for (int ni = 0; ni < 8; ni++)
        #pragma unroll
        for (int r = 0; r < 4; r++) acc[ni][r] = 0.f;

    int nIter = Kd >> 5;

    auto loadTile = [&](int it, int buf) {
        int k0 = it * 32;
        float* Ab = As + buf * MOE_A_ELEMS;
        float* Bb = Bs + buf * MOE_B_ELEMS;
        #pragma unroll
        for (int t = 0; t < 2; t++) {             // A: 64 rows x 8 chunks = 512
            int id = tid + t * 256;
            int ar = id >> 3, ac4 = id & 7;
            cp16(smem_u32(Ab + ar * A_LD + ac4 * 4),
                 Asrc + (size_t)prow[ar] * Kd + k0 + ac4 * 4);
        }
        #pragma unroll
        for (int t = 0; t < 4; t++) {             // B: 32 rows x 32 chunks = 1024
            int id = tid + t * 256;
            int br = id >> 5, bc4 = id & 31;
            cp16(smem_u32(Bb + br * B_LD + bc4 * 4),
                 Bw + (size_t)(k0 + br) * Nd + bc4 * 4);
        }
    };

    loadTile(0, 0);
    asm volatile("cp.async.commit_group;");

    for (int it = 0; it < nIter; it++) {
        int buf = it & 1;
        if (it + 1 < nIter) {
            loadTile(it + 1, buf ^ 1);
            asm volatile("cp.async.commit_group;");
            asm volatile("cp.async.wait_group 1;");
        } else {
            asm volatile("cp.async.wait_group 0;");
        }
        __syncthreads();

        const float* Ab = As + buf * MOE_A_ELEMS;
        const float* Bb = Bs + buf * MOE_B_ELEMS;
        #pragma unroll
        for (int ks = 0; ks < 4; ks++) {
            int kk = ks * 8;
            const float* ap = Ab + (wm * 16 + lr) * A_LD + kk + lc;
            uint32_t ah[4], al[4];
            f2tf2(ap[0],            ah[0], al[0]);
            f2tf2(ap[8 * A_LD],     ah[1], al[1]);
            f2tf2(ap[4],            ah[2], al[2]);
            f2tf2(ap[8 * A_LD + 4], ah[3], al[3]);
            #pragma unroll
            for (int ni = 0; ni < 8; ni++) {
                const float* bp = Bb + (kk + lc) * B_LD + wn * 64 + ni * 8 + lr;
                uint32_t bh[2], bl[2];
                f2tf2(bp[0], bh[0], bl[0]);
                f2tf2(bp[4 * B_LD], bh[1], bl[1]);
                mma_tf32(acc[ni], ah, bh);
                mma_tf32(acc[ni], al, bh);
                mma_tf32(acc[ni], ah, bl);
            }
        }
        __syncthreads();
    }

    int colBase = blockIdx.x * 128 + wn * 64;
    int tr0 = wm * 16 + lr;
    #pragma unroll
    for (int ni = 0; ni < 8; ni++) {
        int gc = colBase + ni * 8 + 2 * lc;
        if (tr0 < nt) {
            if (which == 1) {
                float* o = g_hid + (size_t)ps[tr0] * Ii + gc;
                o[0] = gelu_f(acc[ni][0]); o[1] = gelu_f(acc[ni][1]);
            } else {
                float* o = g_po + (size_t)ps[tr0] * Cc + gc;
                o[0] = acc[ni][0]; o[1] = acc[ni][1];
            }
        }
        if (tr0 + 8 < nt) {
            if (which == 1) {
                float* o = g_hid + (size_t)ps[tr0 + 8] * Ii + gc;
                o[0] = gelu_f(acc[ni][2]); o[1] = gelu_f(acc[ni][3]);
            } else {
                float* o = g_po + (size_t)ps[tr0 + 8] * Cc + gc;
                o[0] = acc[ni][2]; o[1] = acc[ni][3];
            }
        }
    }
}

// ---------------- scalar GEMM (router: N=32) ----------------
__global__ void gemm_kernel(const float* __restrict__ A, const float* __restrict__ B,
                            const float* __restrict__ R, float* __restrict__ C,
                            int M, int N, int Kd) {
    __shared__ float As2[16][68];
    __shared__ float Bs2[16][68];
    int tid = threadIdx.x;
    int tx = tid & 15;
    int ty = tid >> 4;
    int rowBase = blockIdx.y * 64;
    int colBase = blockIdx.x * 64;
    float acc[8][4];
    #pragma unroll
    for (int i = 0; i < 8; i++)
        #pragma unroll
        for (int j = 0; j < 4; j++) acc[i][j] = 0.f;

    int lkA = tid & 15, lm8 = tid >> 4;
    int lnB = tid & 63, lkB = tid >> 6;

    for (int k0 = 0; k0 < Kd; k0 += 16) {
        #pragma unroll
        for (int mi = 0; mi < 8; mi++) {
            int m = lm8 * 8 + mi;
            int gr = rowBase + m, gk = k0 + lkA;
            As2[lkA][m] = (gr < M && gk < Kd) ? A[(size_t)gr * Kd + gk] : 0.f;
        }
        #pragma unroll
        for (int ki = 0; ki < 8; ki++) {
            int k = lkB * 8 + ki;
            int gk = k0 + k, gc = colBase + lnB;
            Bs2[k][lnB] = (gk < Kd && gc < N) ? B[(size_t)gk * N + gc] : 0.f;
        }
        __syncthreads();
        #pragma unroll
        for (int k = 0; k < 16; k++) {
            float a[8], bb[4];
            #pragma unroll
            for (int i = 0; i < 8; i++) a[i] = As2[k][ty * 8 + i];
            #pragma unroll
            for (int j = 0; j < 4; j++) bb[j] = Bs2[k][tx * 4 + j];
            #pragma unroll
            for (int i = 0; i < 8; i++)
                #pragma unroll
                for (int j = 0; j < 4; j++) acc[i][j] = fmaf(a[i], bb[j], acc[i][j]);
        }
        __syncthreads();
    }
    #pragma unroll
    for (int i = 0; i < 8; i++) {
        int gr = rowBase + ty * 8 + i;
        if (gr >= M) continue;
        #pragma unroll
        for (int j = 0; j < 4; j++) {
            int gc = colBase + tx * 4 + j;
            if (gc >= N) continue;
            float val = acc[i][j];
            if (R) val += R[(size_t)gr * N + gc];
            C[(size_t)gr * N + gc] = val;
        }
    }
}

// ---------------- flash-style tensor-core attention ----------------
// Block per (64-q tile, b*h). 128 threads = 4 warps, each owning 16 q rows.
// S = Q@K^T via tf32x3 mma; online softmax; O += P@V via tf32x3 mma.
#define FA_LD 68
#define FA_SMEM (4 * 64 * FA_LD * 4)

__global__ __launch_bounds__(128, 1)
void fattn_kernel(const float* __restrict__ Q, const float* __restrict__ Km,
                  const float* __restrict__ Vm, float* __restrict__ AO) {
    extern __shared__ float fs[];
    float* Qs = fs;
    float* Ks = fs + 64 * FA_LD;
    float* Vs = fs + 2 * 64 * FA_LD;   // transposed: [d][key]
    float* Ps = fs + 3 * 64 * FA_LD;

    int qt = blockIdx.x;
    int bh = blockIdx.y;
    int bb = bh >> 3, hh = bh & 7;
    int q0 = qt * 64;

    int tid = threadIdx.x;
    int lane = tid & 31;
    int warp = tid >> 5;
    int lr = lane >> 2;
    int lc = lane & 3;
    int rbase = warp * 16;

    // load Q tile (64 x 64), 16 float4-chunks per row
    #pragma unroll
    for (int t = 0; t < 8; t++) {
        int id = tid + t * 128;
        int r = id >> 4, c4 = id & 15;
        cp16(smem_u32(Qs + r * FA_LD + c4 * 4),
             Q + (size_t)(bb * Tt + q0 + r) * Cc + hh * Dd + c4 * 4);
    }
    asm volatile("cp.async.commit_group;");

    float m_a = -1e30f, m_b = -1e30f, l_a = 0.f, l_b = 0.f;
    float o[8][4];
    #pragma unroll
    for (int ni = 0; ni < 8; ni++)
        #pragma unroll
        for (int r = 0; r < 4; r++) o[ni][r] = 0.f;

    for (int jt = 0; jt <= qt; jt++) {
        int j0 = jt * 64;
        // K tile via cp.async
        #pragma unroll
        for (int t = 0; t < 8; t++) {
            int id = tid + t * 128;
            int r = id >> 4, c4 = id & 15;
            cp16(smem_u32(Ks + r * FA_LD + c4 * 4),
                 Km + (size_t)(bb * Tt + j0 + r) * Cc + hh * Dd + c4 * 4);
        }
        asm volatile("cp.async.commit_group;");
        // V tile transposed (scalar stores)
        #pragma unroll
        for (int t = 0; t < 8; t++) {
            int id = tid + t * 128;
            int r = id >> 4, c4 = id & 15;
            float4 v = *reinterpret_cast<const float4*>(
                Vm + (size_t)(bb * Tt + j0 + r) * Cc + hh * Dd + c4 * 4);
            Vs[(c4 * 4 + 0) * FA_LD + r] = v.x;
            Vs[(c4 * 4 + 1) * FA_LD + r] = v.y;
            Vs[(c4 * 4 + 2) * FA_LD + r] = v.z;
            Vs[(c4 * 4 + 3) * FA_LD + r] = v.w;
        }
        asm volatile("cp.async.wait_group 0;");
        __syncthreads();

        // ---- S = Q @ K^T (per warp: 16 x 64) ----
        float s[8][4];
        #pragma unroll
        for (int ni = 0; ni < 8; ni++)
            #pragma unroll
            for (int r = 0; r < 4; r++) s[ni][r] = 0.f;

        #pragma unroll
        for (int ks = 0; ks < 8; ks++) {
            int kk = ks * 8;
            const float* ap = Qs + (rbase + lr) * FA_LD + kk + lc;
            uint32_t ah[4], al[4];
            f2tf2(ap[0],              ah[0], al[0]);
            f2tf2(ap[8 * FA_LD],      ah[1], al[1]);
            f2tf2(ap[4],              ah[2], al[2]);
            f2tf2(ap[8 * FA_LD + 4],  ah[3], al[3]);
            #pragma unroll
            for (int ni = 0; ni < 8; ni++) {
                const float* bp = Ks + (ni * 8 + lr) * FA_LD + kk + lc;
                uint32_t bhh[2], bll[2];
                f2tf2(bp[0], bhh[0], bll[0]);
                f2tf2(bp[4], bhh[1], bll[1]);
                mma_tf32(s[ni], ah, bhh);
                mma_tf32(s[ni], al, bhh);
                mma_tf32(s[ni], ah, bll);
            }
        }

        // scale + causal mask
        int qga = q0 + rbase + lr;
        int qgb = qga + 8;
        #pragma unroll
        for (int ni = 0; ni < 8; ni++) {
            int c0 = j0 + ni * 8 + 2 * lc;
            int c1 = c0 + 1;
            s[ni][0] = (c0 <= qga) ? s[ni][0] * 0.125f : -1e30f;
            s[ni][1] = (c1 <= qga) ? s[ni][1] * 0.125f : -1e30f;
            s[ni][2] = (c0 <= qgb) ? s[ni][2] * 0.125f : -1e30f;
            s[ni][3] = (c1 <= qgb) ? s[ni][3] * 0.125f : -1e30f;
        }

        // row max (rows lr -> regs 0,1 ; lr+8 -> regs 2,3)
        float mxa = -1e30f, mxb = -1e30f;
        #pragma unroll
        for (int ni = 0; ni < 8; ni++) {
            mxa = fmaxf(mxa, fmaxf(s[ni][0], s[ni][1]));
            mxb = fmaxf(mxb, fmaxf(s[ni][2], s[ni][3]));
        }
        mxa = fmaxf(mxa, __shfl_xor_sync(0xffffffff, mxa, 1));
        mxa = fmaxf(mxa, __shfl_xor_sync(0xffffffff, mxa, 2));
        mxb = fmaxf(mxb, __shfl_xor_sync(0xffffffff, mxb, 1));
        mxb = fmaxf(mxb, __shfl_xor_sync(0xffffffff, mxb, 2));

        float mna = fmaxf(m_a, mxa);
        float mnb = fmaxf(m_b, mxb);
        float sca = __expf(m_a - mna);
        float scb = __expf(m_b - mnb);

        // exponentiate + row sums, store P
        float sa = 0.f, sb = 0.f;
        #pragma unroll
        for (int ni = 0; ni < 8; ni++) {
            float p0 = __expf(s[ni][0] - mna);
            float p1 = __expf(s[ni][1] - mna);
            float p2 = __expf(s[ni][2] - mnb);
            float p3 = __expf(s[ni][3] - mnb);
            sa += p0 + p1; sb += p2 + p3;
            int cc0 = ni * 8 + 2 * lc;
            Ps[(rbase + lr) * FA_LD + cc0]     = p0;
            Ps[(rbase + lr) * FA_LD + cc0 + 1] = p1;
            Ps[(rbase + lr + 8) * FA_LD + cc0]     = p2;
            Ps[(rbase + lr + 8) * FA_LD + cc0 + 1] = p3;
        }
        sa += __shfl_xor_sync(0xffffffff, sa, 1);
        sa += __shfl_xor_sync(0xffffffff, sa, 2);
        sb += __shfl_xor_sync(0xffffffff, sb, 1);
        sb += __shfl_xor_sync(0xffffffff, sb, 2);

        l_a = l_a * sca + sa;
        l_b = l_b * scb + sb;
        m_a = mna; m_b = mnb;

        // rescale O
        #pragma unroll
        for (int ni = 0; ni < 8; ni++) {
            o[ni][0] *= sca; o[ni][1] *= sca;
            o[ni][2] *= scb; o[ni][3] *= scb;
        }
        __syncwarp();

        // ---- O += P @ V  (k = 64 keys) ----
        #pragma unroll
        for (int ks = 0; ks < 8; ks++) {
            int kk = ks * 8;
            const float* ap = Ps + (rbase + lr) * FA_LD + kk + lc;
            uint32_t ah[4], al[4];
            f2tf2(ap[0],              ah[0], al[0]);
            f2tf2(ap[8 * FA_LD],      ah[1], al[1]);
            f2tf2(ap[4],              ah[2], al[2]);
            f2tf2(ap[8 * FA_LD + 4],  ah[3], al[3]);
            #pragma unroll
            for (int ni = 0; ni < 8; ni++) {
                const float* bp = Vs + (ni * 8 + lr) * FA_LD + kk + lc;
                uint32_t bhh[2], bll[2];
                f2tf2(bp[0], bhh[0], bll[0]);
                f2tf2(bp[4], bhh[1], bll[1]);
                mma_tf32(o[ni], ah, bhh);
                mma_tf32(o[ni], al, bhh);
                mma_tf32(o[ni], ah, bll);
            }
        }
        __syncthreads();
    }

    float ia = 1.f / l_a;
    float ib = 1.f / l_b;
    int qra = bb * Tt + q0 + rbase + lr;
    #pragma unroll
    for (int ni = 0; ni < 8; ni++) {
        int gc = hh * Dd + ni * 8 + 2 * lc;
        *reinterpret_cast<float2*>(AO + (size_t)qra * Cc + gc) =
            make_float2(o[ni][0] * ia, o[ni][1] * ia);
        *reinterpret_cast<float2*>(AO + (size_t)(qra + 8) * Cc + gc) =
            make_float2(o[ni][2] * ib, o[ni][3] * ib);
    }
}

// ---------------- routing ----------------
__global__ void zero_cnt_kernel() { if (threadIdx.x < Ee) g_cnt[threadIdx.x] = 0; }

__global__ void topk_kernel(const float* __restrict__ RL) {
    int t = blockIdx.x * blockDim.x + threadIdx.x;
    if (t >= NTOK) return;
    const float* r = RL + (size_t)t * Ee;
    int i1 = 0; float v1 = r[0];
    for (int e = 1; e < Ee; e++) if (r[e] > v1) { v1 = r[e]; i1 = e; }
    int i2 = -1; float v2 = -3.4e38f;
    for (int e = 0; e < Ee; e++) { if (e == i1) continue; if (r[e] > v2) { v2 = r[e]; i2 = e; } }
    float e1 = 1.f, e2 = __expf(v2 - v1);
    float inv = 1.f / (e1 + e2);
    g_sel[t * 2] = i1; g_sel[t * 2 + 1] = i2;
    g_rw[t * 2] = e1 * inv; g_rw[t * 2 + 1] = e2 * inv;
    int s1 = atomicAdd(&g_cnt[i1], 1); g_bucket[i1 * NPAIR + s1] = t * 2;
    int s2 = atomicAdd(&g_cnt[i2], 1); g_bucket[i2 * NPAIR + s2] = t * 2 + 1;
}

// ---------------- scatter + combine ----------------
__global__ void feo_scatter(float* __restrict__ FEO) {
    int p = blockIdx.x;
    int t = p >> 1, e = g_sel[p];
    float* dst = FEO + ((size_t)t * Ee + e) * Cc;
    const float* src = g_po + (size_t)p * Cc;
    for (int c = threadIdx.x; c < Cc; c += 128) dst[c] = src[c];
}

__global__ void moe_combine() {
    int t = blockIdx.x;
    float w0 = g_rw[t * 2], w1r = g_rw[t * 2 + 1];
    float* hrow = g_h + (size_t)t * Cc;
    const float* p0 = g_po + (size_t)(t * 2) * Cc;
    const float* p1 = g_po + (size_t)(t * 2 + 1) * Cc;
    for (int c = threadIdx.x; c < Cc; c += 128)
        hrow[c] += w0 * p0[c] + w1r * p1[c];
}

// ---------------- launch ----------------
extern "C" void kernel_launch(void* const* d_in, const int* in_sizes, int n_in,
                              void* d_out, int out_size) {
    const int*   ids  = (const int*)d_in[0];
    const float* emb  = (const float*)d_in[1];
    const float* wq   = (const float*)d_in[2];
    const float* wk   = (const float*)d_in[3];
    const float* wv   = (const float*)d_in[4];
    const float* wo   = (const float*)d_in[5];
    const float* gate = (const float*)d_in[6];
    const float* w1   = (const float*)d_in[7];
    const float* w2   = (const float*)d_in[8];
    const float* g1   = (const float*)d_in[9];
    const float* b1   = (const float*)d_in[10];
    const float* g2   = (const float*)d_in[11];
    const float* b2   = (const float*)d_in[12];
    const float* lm   = (const float*)d_in[13];
    float* out = (float*)d_out;

    float *p_h, *p_x, *p_q, *p_k, *p_v, *p_ao, *p_x2, *p_rl, *p_hid;
    cudaGetSymbolAddress((void**)&p_h,  g_h);
    cudaGetSymbolAddress((void**)&p_x,  g_x);
    cudaGetSymbolAddress((void**)&p_q,  g_q);
    cudaGetSymbolAddress((void**)&p_k,  g_k);
    cudaGetSymbolAddress((void**)&p_v,  g_v);
    cudaGetSymbolAddress((void**)&p_ao, g_ao);
    cudaGetSymbolAddress((void**)&p_x2, g_x2);
    cudaGetSymbolAddress((void**)&p_rl, g_rl);
    cudaGetSymbolAddress((void**)&p_hid, g_hid);

    cudaFuncSetAttribute(mma_gemm<1>, cudaFuncAttributeMaxDynamicSharedMemorySize,
                         GEMM_SMEM_BYTES);
    cudaFuncSetAttribute(mma_gemm<0>, cudaFuncAttributeMaxDynamicSharedMemorySize,
                         GEMM_SMEM_BYTES);
    cudaFuncSetAttribute(moe_mma, cudaFuncAttributeMaxDynamicSharedMemorySize,
                         MOE_SMEM_BYTES);
    cudaFuncSetAttribute(fattn_kernel, cudaFuncAttributeMaxDynamicSharedMemorySize,
                         FA_SMEM);

    const size_t L_LOG = (size_t)NTOK * Vv;
    const size_t L_FEO = (size_t)NTOK * Ee * Cc;
    const size_t L_RL  = (size_t)NTOK * Ee;
    const size_t L_X2  = (size_t)NTOK * Cc;
    const size_t OFF_FEO = L_LOG;
    const size_t OFF_RL  = OFF_FEO + L_FEO;
    const size_t OFF_X2  = OFF_RL + L_RL;
    bool full = (size_t)out_size >= OFF_X2 + L_X2;

    embed_kernel<<<NTOK, 128>>>(ids, emb, p_h);
    ln_kernel<<<NTOK, 128>>>(p_h, g1, b1, p_x);

    mma_gemm<1><<<dim3(Cc / 128, NTOK / 128, 3), 256, GEMM_SMEM_BYTES>>>(
        p_x, wq, wk, wv, nullptr, p_q, p_k, p_v, NTOK, Cc, Cc);

    fattn_kernel<<<dim3(Tt / 64, Bsz * Hh), 128, FA_SMEM>>>(p_q, p_k, p_v, p_ao);

    mma_gemm<1><<<dim3(Cc / 128, NTOK / 128, 1), 256, GEMM_SMEM_BYTES>>>(
        p_ao, wo, wo, wo, p_h, p_h, p_h, p_h, NTOK, Cc, Cc);

    ln_kernel<<<NTOK, 128>>>(p_h, g2, b2, p_x2);

    gemm_kernel<<<dim3(1, NTOK / 64), 128>>>(p_x2, gate, nullptr, p_rl, NTOK, Ee, Cc);

    zero_cnt_kernel<<<1, 32>>>();
    topk_kernel<<<NTOK / 128, 128>>>(p_rl);

    moe_mma<<<dim3(Ii / 128, NPAIR / MOE_M, Ee), 256, MOE_SMEM_BYTES>>>(
        p_x2, w1, Cc, Ii, 1);
    moe_mma<<<dim3(Cc / 128, NPAIR / MOE_M, Ee), 256, MOE_SMEM_BYTES>>>(
        p_hid, w2, Ii, Cc, 2);

    if (full) {
        cudaMemsetAsync(out + OFF_FEO, 0, L_FEO * sizeof(float));
        feo_scatter<<<NPAIR, 128>>>(out + OFF_FEO);
    }
    moe_combine<<<NTOK, 128>>>();

    mma_gemm<0><<<dim3(Vv / 128, NTOK / 128, 1), 256, GEMM_SMEM_BYTES>>>(
        p_h, lm, lm, lm, nullptr, out, out, out, NTOK, Vv, Cc);

    if (full) {
        cudaMemcpyAsync(out + OFF_RL, p_rl, L_RL * sizeof(float), cudaMemcpyDeviceToDevice);
        cudaMemcpyAsync(out + OFF_X2, p_x2, L_X2 * sizeof(float), cudaMemcpyDeviceToDevice);
    }
}

// round 7
// speedup vs baseline: 3.1779x; 1.2564x over previous
#include <cuda_runtime.h>
#include <cuda_bf16.h>
#include <math.h>
#include <stdint.h>

#define Bsz 4
#define Tt 512
#define Cc 512
#define Hh 8
#define Dd 64
#define Ee 32
#define Ii 2048
#define Kk 2
#define Vv 32000
#define NTOK 2048
#define NPAIR 4096

// ---------------- scratch ----------------
__device__ float g_h   [NTOK * Cc];
__device__ float g_x   [NTOK * Cc];
__device__ float g_q   [NTOK * Cc];
__device__ float g_k   [NTOK * Cc];
__device__ float g_v   [NTOK * Cc];
__device__ float g_ao  [NTOK * Cc];
__device__ float g_x2  [NTOK * Cc];
__device__ float g_rl  [NTOK * Ee];
__device__ float g_hid [NPAIR * Ii];
__device__ float g_po  [NPAIR * Cc];
__device__ int   g_sel [NPAIR];
__device__ float g_rw  [NPAIR];
__device__ int   g_cnt [Ee];
__device__ int   g_bucket[Ee * NPAIR];

// ---------------- embedding ----------------
__global__ void embed_kernel(const int* __restrict__ ids, const float* __restrict__ emb,
                             float* __restrict__ H) {
    int t = blockIdx.x;
    int id = ids[t];
    const float* src = emb + (size_t)id * Cc;
    float* dst = H + (size_t)t * Cc;
    for (int c = threadIdx.x; c < Cc; c += blockDim.x) dst[c] = src[c];
}

// ---------------- layernorm ----------------
__global__ void ln_kernel(const float* __restrict__ X, const float* __restrict__ g,
                          const float* __restrict__ b, float* __restrict__ Y) {
    int t = blockIdx.x, tid = threadIdx.x;
    const float* row = X + (size_t)t * Cc;
    __shared__ float red[128];
    float s = 0.f;
    for (int c = tid; c < Cc; c += 128) s += row[c];
    red[tid] = s; __syncthreads();
    for (int k = 64; k > 0; k >>= 1) { if (tid < k) red[tid] += red[tid + k]; __syncthreads(); }
    float mu = red[0] / Cc; __syncthreads();
    float s2 = 0.f;
    for (int c = tid; c < Cc; c += 128) { float d = row[c] - mu; s2 += d * d; }
    red[tid] = s2; __syncthreads();
    for (int k = 64; k > 0; k >>= 1) { if (tid < k) red[tid] += red[tid + k]; __syncthreads(); }
    float inv = rsqrtf(red[0] / Cc + 1e-5f);
    float* out = Y + (size_t)t * Cc;
    for (int c = tid; c < Cc; c += 128) out[c] = (row[c] - mu) * inv * g[c] + b[c];
}

// ---------------- mma helpers ----------------
__device__ __forceinline__ uint32_t smem_u32(const void* p) {
    uint32_t a;
    asm("{ .reg .u64 t; cvta.to.shared.u64 t, %1; cvt.u32.u64 %0, t; }" : "=r"(a) : "l"(p));
    return a;
}
__device__ __forceinline__ void cp16(uint32_t dst, const void* src) {
    asm volatile("cp.async.cg.shared.global [%0], [%1], 16;" :: "r"(dst), "l"(src));
}
__device__ __forceinline__ void f2tf2(float x, uint32_t& hi, uint32_t& lo) {
    uint32_t h;
    asm("cvt.rna.tf32.f32 %0, %1;" : "=r"(h) : "f"(x));
    float r = x - __uint_as_float(h);
    uint32_t l;
    asm("cvt.rna.tf32.f32 %0, %1;" : "=r"(l) : "f"(r));
    hi = h; lo = l;
}
__device__ __forceinline__ uint32_t f2tf(float f) {
    uint32_t u;
    asm("cvt.rna.tf32.f32 %0, %1;" : "=r"(u) : "f"(f));
    return u;
}
__device__ __forceinline__ void mma_tf32(float* d, const uint32_t* a, const uint32_t* b) {
    asm volatile(
        "mma.sync.aligned.m16n8k8.row.col.f32.tf32.tf32.f32 "
        "{%0,%1,%2,%3}, {%4,%5,%6,%7}, {%8,%9}, {%0,%1,%2,%3};"
        : "+f"(d[0]), "+f"(d[1]), "+f"(d[2]), "+f"(d[3])
        : "r"(a[0]), "r"(a[1]), "r"(a[2]), "r"(a[3]), "r"(b[0]), "r"(b[1]));
}

// ---------------- tf32(x3) tensor-core GEMM ----------------
// SWAP=1: blockIdx.x indexes rows, blockIdx.y indexes cols (so consecutive
// blocks share the same B column strip -> L2 dedup for tall grids).
#define A_LD 36
#define B_LD 136
#define SMEM_A_ELEMS (128 * A_LD)
#define SMEM_B_ELEMS (32 * B_LD)
#define GEMM_SMEM_BYTES ((2 * SMEM_A_ELEMS + 2 * SMEM_B_ELEMS) * 4)

template<int XTRA, int SWAP>
__global__ __launch_bounds__(256, 2)
void mma_gemm(const float* __restrict__ A,
              const float* __restrict__ B0, const float* __restrict__ B1,
              const float* __restrict__ B2,
              const float* __restrict__ R,
              float* __restrict__ C0, float* __restrict__ C1, float* __restrict__ C2,
              int M, int N, int K) {
    extern __shared__ float sm[];
    float* As = sm;
    float* Bs = sm + 2 * SMEM_A_ELEMS;

    const float* B = (blockIdx.z == 0) ? B0 : ((blockIdx.z == 1) ? B1 : B2);
    float* C = (blockIdx.z == 0) ? C0 : ((blockIdx.z == 1) ? C1 : C2);

    int tid = threadIdx.x;
    int lane = tid & 31;
    int warp = tid >> 5;
    int wm = warp & 1;
    int wn = warp >> 1;
    int rowBase = (SWAP ? blockIdx.x : blockIdx.y) * 128;
    int colBase = (SWAP ? blockIdx.y : blockIdx.x) * 128;

    float acc[4][4][4];
    #pragma unroll
    for (int mi = 0; mi < 4; mi++)
        #pragma unroll
        for (int ni = 0; ni < 4; ni++)
            #pragma unroll
            for (int r = 0; r < 4; r++) acc[mi][ni][r] = 0.f;

    int nIter = K >> 5;

    auto loadTile = [&](int it, int buf) {
        int k0 = it * 32;
        float* Ab = As + buf * SMEM_A_ELEMS;
        float* Bb = Bs + buf * SMEM_B_ELEMS;
        #pragma unroll
        for (int t = 0; t < 4; t++) {
            int id = tid + t * 256;
            int ar = id >> 3, ac4 = id & 7;
            cp16(smem_u32(Ab + ar * A_LD + ac4 * 4),
                 A + (size_t)(rowBase + ar) * K + k0 + ac4 * 4);
            int br = id >> 5, bc4 = id & 31;
            cp16(smem_u32(Bb + br * B_LD + bc4 * 4),
                 B + (size_t)(k0 + br) * N + colBase + bc4 * 4);
        }
    };

    loadTile(0, 0);
    asm volatile("cp.async.commit_group;");

    int rbase = wm * 64;
    int cbase = wn * 32;
    int lr = lane >> 2;
    int lc = lane & 3;

    for (int it = 0; it < nIter; it++) {
        int buf = it & 1;
        if (it + 1 < nIter) {
            loadTile(it + 1, buf ^ 1);
            asm volatile("cp.async.commit_group;");
            asm volatile("cp.async.wait_group 1;");
        } else {
            asm volatile("cp.async.wait_group 0;");
        }
        __syncthreads();

        const float* Ab = As + buf * SMEM_A_ELEMS;
        const float* Bb = Bs + buf * SMEM_B_ELEMS;
        #pragma unroll
        for (int ks = 0; ks < 4; ks++) {
            int kk = ks * 8;
            uint32_t bh[4][2], bl[4][2];
            #pragma unroll
            for (int ni = 0; ni < 4; ni++) {
                const float* bp = Bb + (kk + lc) * B_LD + cbase + ni * 8 + lr;
                if (XTRA) {
                    f2tf2(bp[0], bh[ni][0], bl[ni][0]);
                    f2tf2(bp[4 * B_LD], bh[ni][1], bl[ni][1]);
                } else {
                    bh[ni][0] = f2tf(bp[0]);
                    bh[ni][1] = f2tf(bp[4 * B_LD]);
                }
            }
            #pragma unroll
            for (int mi = 0; mi < 4; mi++) {
                const float* ap = Ab + (rbase + mi * 16 + lr) * A_LD + kk + lc;
                uint32_t ah[4], al[4];
                if (XTRA) {
                    f2tf2(ap[0],            ah[0], al[0]);
                    f2tf2(ap[8 * A_LD],     ah[1], al[1]);
                    f2tf2(ap[4],            ah[2], al[2]);
                    f2tf2(ap[8 * A_LD + 4], ah[3], al[3]);
                } else {
                    ah[0] = f2tf(ap[0]);
                    ah[1] = f2tf(ap[8 * A_LD]);
                    ah[2] = f2tf(ap[4]);
                    ah[3] = f2tf(ap[8 * A_LD + 4]);
                }
                #pragma unroll
                for (int ni = 0; ni < 4; ni++) {
                    mma_tf32(acc[mi][ni], ah, bh[ni]);
                    if (XTRA) {
                        mma_tf32(acc[mi][ni], al, bh[ni]);
                        mma_tf32(acc[mi][ni], ah, bl[ni]);
                    }
                }
            }
        }
        __syncthreads();
    }

    #pragma unroll
    for (int mi = 0; mi < 4; mi++) {
        int gr0 = rowBase + rbase + mi * 16 + lr;
        #pragma unroll
        for (int ni = 0; ni < 4; ni++) {
            int gc = colBase + cbase + ni * 8 + 2 * lc;
            float2 v0 = make_float2(acc[mi][ni][0], acc[mi][ni][1]);
            float2 v1 = make_float2(acc[mi][ni][2], acc[mi][ni][3]);
            if (R) {
                const float2 r0 = *reinterpret_cast<const float2*>(R + (size_t)gr0 * N + gc);
                const float2 r1 = *reinterpret_cast<const float2*>(R + (size_t)(gr0 + 8) * N + gc);
                v0.x += r0.x; v0.y += r0.y; v1.x += r1.x; v1.y += r1.y;
            }
            *reinterpret_cast<float2*>(C + (size_t)gr0 * N + gc) = v0;
            *reinterpret_cast<float2*>(C + (size_t)(gr0 + 8) * N + gc) = v1;
        }
    }
}

// ---------------- MoE tensor-core GEMMs (64-token x 128-col tiles) ----------------
#define MOE_M 64
#define MOE_A_ELEMS (MOE_M * A_LD)
#define MOE_B_ELEMS (32 * B_LD)
#define MOE_SMEM_BYTES ((2 * MOE_A_ELEMS + 2 * MOE_B_ELEMS) * 4 + 2 * MOE_M * 4)

__device__ __forceinline__ float gelu_f(float x) {
    return 0.5f * x * (1.f + erff(x * 0.70710678118654752f));
}

// which==1: hidden = gelu(gather(X2) @ W1[e]);  K=Cc, N=Ii
// which==2: po = gather(g_hid) @ W2[e];          K=Ii, N=Cc
template<int XTRA>
__global__ __launch_bounds__(256, 2)
void moe_mma(const float* __restrict__ Asrc, const float* __restrict__ W,
             int Kd, int Nd, int which) {
    int e = blockIdx.z;
    int n = g_cnt[e];
    int t0 = blockIdx.y * MOE_M;
    if (t0 >= n) return;
    int nt = min(MOE_M, n - t0);

    extern __shared__ float sm[];
    float* As = sm;
    float* Bs = sm + 2 * MOE_A_ELEMS;
    int* ps = (int*)(Bs + 2 * MOE_B_ELEMS);
    int* prow = ps + MOE_M;

    int tid = threadIdx.x;
    if (tid < MOE_M) {
        int p = (tid < nt) ? g_bucket[e * NPAIR + t0 + tid] : -1;
        ps[tid] = p;
        int r = (p >= 0) ? p : 0;
        prow[tid] = (which == 1) ? (r >> 1) : r;
    }
    __syncthreads();

    const float* Bw = W + (size_t)e * Cc * Ii + blockIdx.x * 128;

    int lane = tid & 31;
    int warp = tid >> 5;
    int wm = warp >> 1;
    int wn = warp & 1;
    int lr = lane >> 2;
    int lc = lane & 3;

    float acc[8][4];
    #pragma unroll
    for (int ni = 0; ni < 8; ni++)
        #pragma unroll
        for (int r = 0; r < 4; r++) acc[ni][r] = 0.f;

    int nIter = Kd >> 5;

    auto loadTile = [&](int it, int buf) {
        int k0 = it * 32;
        float* Ab = As + buf * MOE_A_ELEMS;
        float* Bb = Bs + buf * MOE_B_ELEMS;
        #pragma unroll
        for (int t = 0; t < 2; t++) {
            int id = tid + t * 256;
            int ar = id >> 3, ac4 = id & 7;
            cp16(smem_u32(Ab + ar * A_LD + ac4 * 4),
                 Asrc + (size_t)prow[ar] * Kd + k0 + ac4 * 4);
        }
        #pragma unroll
        for (int t = 0; t < 4; t++) {
            int id = tid + t * 256;
            int br = id >> 5, bc4 = id & 31;
            cp16(smem_u32(Bb + br * B_LD + bc4 * 4),
                 Bw + (size_t)(k0 + br) * Nd + bc4 * 4);
        }
    };

    loadTile(0, 0);
    asm volatile("cp.async.commit_group;");

    for (int it = 0; it < nIter; it++) {
        int buf = it & 1;
        if (it + 1 < nIter) {
            loadTile(it + 1, buf ^ 1);
            asm volatile("cp.async.commit_group;");
            asm volatile("cp.async.wait_group 1;");
        } else {
            asm volatile("cp.async.wait_group 0;");
        }
        __syncthreads();

        const float* Ab = As + buf * MOE_A_ELEMS;
        const float* Bb = Bs + buf * MOE_B_ELEMS;
        #pragma unroll
        for (int ks = 0; ks < 4; ks++) {
            int kk = ks * 8;
            const float* ap = Ab + (wm * 16 + lr) * A_LD + kk + lc;
            uint32_t ah[4], al[4];
            if (XTRA) {
                f2tf2(ap[0],            ah[0], al[0]);
                f2tf2(ap[8 * A_LD],     ah[1], al[1]);
                f2tf2(ap[4],            ah[2], al[2]);
                f2tf2(ap[8 * A_LD + 4], ah[3], al[3]);
            } else {
                ah[0] = f2tf(ap[0]);
                ah[1] = f2tf(ap[8 * A_LD]);
                ah[2] = f2tf(ap[4]);
                ah[3] = f2tf(ap[8 * A_LD + 4]);
            }
            #pragma unroll
            for (int ni = 0; ni < 8; ni++) {
                const float* bp = Bb + (kk + lc) * B_LD + wn * 64 + ni * 8 + lr;
                uint32_t bh[2], bl[2];
                if (XTRA) {
                    f2tf2(bp[0], bh[0], bl[0]);
                    f2tf2(bp[4 * B_LD], bh[1], bl[1]);
                } else {
                    bh[0] = f2tf(bp[0]);
                    bh[1] = f2tf(bp[4 * B_LD]);
                }
                mma_tf32(acc[ni], ah, bh);
                if (XTRA) {
                    mma_tf32(acc[ni], al, bh);
                    mma_tf32(acc[ni], ah, bl);
                }
            }
        }
        __syncthreads();
    }

    int colBase = blockIdx.x * 128 + wn * 64;
    int tr0 = wm * 16 + lr;
    #pragma unroll
    for (int ni = 0; ni < 8; ni++) {
        int gc = colBase + ni * 8 + 2 * lc;
        if (tr0 < nt) {
            if (which == 1) {
                float* o = g_hid + (size_t)ps[tr0] * Ii + gc;
                o[0] = gelu_f(acc[ni][0]); o[1] = gelu_f(acc[ni][1]);
            } else {
                float* o = g_po + (size_t)ps[tr0] * Cc + gc;
                o[0] = acc[ni][0]; o[1] = acc[ni][1];
            }
        }
        if (tr0 + 8 < nt) {
            if (which == 1) {
                float* o = g_hid + (size_t)ps[tr0 + 8] * Ii + gc;
                o[0] = gelu_f(acc[ni][2]); o[1] = gelu_f(acc[ni][3]);
            } else {
                float* o = g_po + (size_t)ps[tr0 + 8] * Cc + gc;
                o[0] = acc[ni][2]; o[1] = acc[ni][3];
            }
        }
    }
}

// ---------------- scalar GEMM (router: N=32) ----------------
__global__ void gemm_kernel(const float* __restrict__ A, const float* __restrict__ B,
                            const float* __restrict__ R, float* __restrict__ C,
                            int M, int N, int Kd) {
    __shared__ float As2[16][68];
    __shared__ float Bs2[16][68];
    int tid = threadIdx.x;
    int tx = tid & 15;
    int ty = tid >> 4;
    int rowBase = blockIdx.y * 64;
    int colBase = blockIdx.x * 64;
    float acc[8][4];
    #pragma unroll
    for (int i = 0; i < 8; i++)
        #pragma unroll
        for (int j = 0; j < 4; j++) acc[i][j] = 0.f;

    int lkA = tid & 15, lm8 = tid >> 4;
    int lnB = tid & 63, lkB = tid >> 6;

    for (int k0 = 0; k0 < Kd; k0 += 16) {
        #pragma unroll
        for (int mi = 0; mi < 8; mi++) {
            int m = lm8 * 8 + mi;
            int gr = rowBase + m, gk = k0 + lkA;
            As2[lkA][m] = (gr < M && gk < Kd) ? A[(size_t)gr * Kd + gk] : 0.f;
        }
        #pragma unroll
        for (int ki = 0; ki < 8; ki++) {
            int k = lkB * 8 + ki;
            int gk = k0 + k, gc = colBase + lnB;
            Bs2[k][lnB] = (gk < Kd && gc < N) ? B[(size_t)gk * N + gc] : 0.f;
        }
        __syncthreads();
        #pragma unroll
        for (int k = 0; k < 16; k++) {
            float a[8], bb[4];
            #pragma unroll
            for (int i = 0; i < 8; i++) a[i] = As2[k][ty * 8 + i];
            #pragma unroll
            for (int j = 0; j < 4; j++) bb[j] = Bs2[k][tx * 4 + j];
            #pragma unroll
            for (int i = 0; i < 8; i++)
                #pragma unroll
                for (int j = 0; j < 4; j++) acc[i][j] = fmaf(a[i], bb[j], acc[i][j]);
        }
        __syncthreads();
    }
    #pragma unroll
    for (int i = 0; i < 8; i++) {
        int gr = rowBase + ty * 8 + i;
        if (gr >= M) continue;
        #pragma unroll
        for (int j = 0; j < 4; j++) {
            int gc = colBase + tx * 4 + j;
            if (gc >= N) continue;
            float val = acc[i][j];
            if (R) val += R[(size_t)gr * N + gc];
            C[(size_t)gr * N + gc] = val;
        }
    }
}

// ---------------- flash-style tensor-core attention ----------------
#define FA_LD 68
#define FA_SMEM (4 * 64 * FA_LD * 4)

__global__ __launch_bounds__(128, 1)
void fattn_kernel(const float* __restrict__ Q, const float* __restrict__ Km,
                  const float* __restrict__ Vm, float* __restrict__ AO) {
    extern __shared__ float fs[];
    float* Qs = fs;
    float* Ks = fs + 64 * FA_LD;
    float* Vs = fs + 2 * 64 * FA_LD;
    float* Ps = fs + 3 * 64 * FA_LD;

    int qt = blockIdx.x;
    int bh = blockIdx.y;
    int bb = bh >> 3, hh = bh & 7;
    int q0 = qt * 64;

    int tid = threadIdx.x;
    int lane = tid & 31;
    int warp = tid >> 5;
    int lr = lane >> 2;
    int lc = lane & 3;
    int rbase = warp * 16;

    #pragma unroll
    for (int t = 0; t < 8; t++) {
        int id = tid + t * 128;
        int r = id >> 4, c4 = id & 15;
        cp16(smem_u32(Qs + r * FA_LD + c4 * 4),
             Q + (size_t)(bb * Tt + q0 + r) * Cc + hh * Dd + c4 * 4);
    }
    asm volatile("cp.async.commit_group;");

    float m_a = -1e30f, m_b = -1e30f, l_a = 0.f, l_b = 0.f;
    float o[8][4];
    #pragma unroll
    for (int ni = 0; ni < 8; ni++)
        #pragma unroll
        for (int r = 0; r < 4; r++) o[ni][r] = 0.f;

    for (int jt = 0; jt <= qt; jt++) {
        int j0 = jt * 64;
        #pragma unroll
        for (int t = 0; t < 8; t++) {
            int id = tid + t * 128;
            int r = id >> 4, c4 = id & 15;
            cp16(smem_u32(Ks + r * FA_LD + c4 * 4),
                 Km + (size_t)(bb * Tt + j0 + r) * Cc + hh * Dd + c4 * 4);
        }
        asm volatile("cp.async.commit_group;");
        #pragma unroll
        for (int t = 0; t < 8; t++) {
            int id = tid + t * 128;
            int r = id >> 4, c4 = id & 15;
            float4 v = *reinterpret_cast<const float4*>(
                Vm + (size_t)(bb * Tt + j0 + r) * Cc + hh * Dd + c4 * 4);
            Vs[(c4 * 4 + 0) * FA_LD + r] = v.x;
            Vs[(c4 * 4 + 1) * FA_LD + r] = v.y;
            Vs[(c4 * 4 + 2) * FA_LD + r] = v.z;
            Vs[(c4 * 4 + 3) * FA_LD + r] = v.w;
        }
        asm volatile("cp.async.wait_group 0;");
        __syncthreads();

        float s[8][4];
        #pragma unroll
        for (int ni = 0; ni < 8; ni++)
            #pragma unroll
            for (int r = 0; r < 4; r++) s[ni][r] = 0.f;

        #pragma unroll
        for (int ks = 0; ks < 8; ks++) {
            int kk = ks * 8;
            const float* ap = Qs + (rbase + lr) * FA_LD + kk + lc;
            uint32_t ah[4], al[4];
            f2tf2(ap[0],              ah[0], al[0]);
            f2tf2(ap[8 * FA_LD],      ah[1], al[1]);
            f2tf2(ap[4],              ah[2], al[2]);
            f2tf2(ap[8 * FA_LD + 4],  ah[3], al[3]);
            #pragma unroll
            for (int ni = 0; ni < 8; ni++) {
                const float* bp = Ks + (ni * 8 + lr) * FA_LD + kk + lc;
                uint32_t bhh[2], bll[2];
                f2tf2(bp[0], bhh[0], bll[0]);
                f2tf2(bp[4], bhh[1], bll[1]);
                mma_tf32(s[ni], ah, bhh);
                mma_tf32(s[ni], al, bhh);
                mma_tf32(s[ni], ah, bll);
            }
        }

        int qga = q0 + rbase + lr;
        int qgb = qga + 8;
        #pragma unroll
        for (int ni = 0; ni < 8; ni++) {
            int c0 = j0 + ni * 8 + 2 * lc;
            int c1 = c0 + 1;
            s[ni][0] = (c0 <= qga) ? s[ni][0] * 0.125f : -1e30f;
            s[ni][1] = (c1 <= qga) ? s[ni][1] * 0.125f : -1e30f;
            s[ni][2] = (c0 <= qgb) ? s[ni][2] * 0.125f : -1e30f;
            s[ni][3] = (c1 <= qgb) ? s[ni][3] * 0.125f : -1e30f;
        }

        float mxa = -1e30f, mxb = -1e30f;
        #pragma unroll
        for (int ni = 0; ni < 8; ni++) {
            mxa = fmaxf(mxa, fmaxf(s[ni][0], s[ni][1]));
            mxb = fmaxf(mxb, fmaxf(s[ni][2], s[ni][3]));
        }
        mxa = fmaxf(mxa, __shfl_xor_sync(0xffffffff, mxa, 1));
        mxa = fmaxf(mxa, __shfl_xor_sync(0xffffffff, mxa, 2));
        mxb = fmaxf(mxb, __shfl_xor_sync(0xffffffff, mxb, 1));
        mxb = fmaxf(mxb, __shfl_xor_sync(0xffffffff, mxb, 2));

        float mna = fmaxf(m_a, mxa);
        float mnb = fmaxf(m_b, mxb);
        float sca = __expf(m_a - mna);
        float scb = __expf(m_b - mnb);

        float sa = 0.f, sb = 0.f;
        #pragma unroll
        for (int ni = 0; ni < 8; ni++) {
            float p0 = __expf(s[ni][0] - mna);
            float p1 = __expf(s[ni][1] - mna);
            float p2 = __expf(s[ni][2] - mnb);
            float p3 = __expf(s[ni][3] - mnb);
            sa += p0 + p1; sb += p2 + p3;
            int cc0 = ni * 8 + 2 * lc;
            Ps[(rbase + lr) * FA_LD + cc0]     = p0;
            Ps[(rbase + lr) * FA_LD + cc0 + 1] = p1;
            Ps[(rbase + lr + 8) * FA_LD + cc0]     = p2;
            Ps[(rbase + lr + 8) * FA_LD + cc0 + 1] = p3;
        }
        sa += __shfl_xor_sync(0xffffffff, sa, 1);
        sa += __shfl_xor_sync(0xffffffff, sa, 2);
        sb += __shfl_xor_sync(0xffffffff, sb, 1);
        sb += __shfl_xor_sync(0xffffffff, sb, 2);

        l_a = l_a * sca + sa;
        l_b = l_b * scb + sb;
        m_a = mna; m_b = mnb;

        #pragma unroll
        for (int ni = 0; ni < 8; ni++) {
            o[ni][0] *= sca; o[ni][1] *= sca;
            o[ni][2] *= scb; o[ni][3] *= scb;
        }
        __syncwarp();

        #pragma unroll
        for (int ks = 0; ks < 8; ks++) {
            int kk = ks * 8;
            const float* ap = Ps + (rbase + lr) * FA_LD + kk + lc;
            uint32_t ah[4], al[4];
            f2tf2(ap[0],              ah[0], al[0]);
            f2tf2(ap[8 * FA_LD],      ah[1], al[1]);
            f2tf2(ap[4],              ah[2], al[2]);
            f2tf2(ap[8 * FA_LD + 4],  ah[3], al[3]);
            #pragma unroll
            for (int ni = 0; ni < 8; ni++) {
                const float* bp = Vs + (ni * 8 + lr) * FA_LD + kk + lc;
                uint32_t bhh[2], bll[2];
                f2tf2(bp[0], bhh[0], bll[0]);
                f2tf2(bp[4], bhh[1], bll[1]);
                mma_tf32(o[ni], ah, bhh);
                mma_tf32(o[ni], al, bhh);
                mma_tf32(o[ni], ah, bll);
            }
        }
        __syncthreads();
    }

    float ia = 1.f / l_a;
    float ib = 1.f / l_b;
    int qra = bb * Tt + q0 + rbase + lr;
    #pragma unroll
    for (int ni = 0; ni < 8; ni++) {
        int gc = hh * Dd + ni * 8 + 2 * lc;
        *reinterpret_cast<float2*>(AO + (size_t)qra * Cc + gc) =
            make_float2(o[ni][0] * ia, o[ni][1] * ia);
        *reinterpret_cast<float2*>(AO + (size_t)(qra + 8) * Cc + gc) =
            make_float2(o[ni][2] * ib, o[ni][3] * ib);
    }
}

// ---------------- routing ----------------
__global__ void zero_cnt_kernel() { if (threadIdx.x < Ee) g_cnt[threadIdx.x] = 0; }

__global__ void topk_kernel(const float* __restrict__ RL) {
    int t = blockIdx.x * blockDim.x + threadIdx.x;
    if (t >= NTOK) return;
    const float* r = RL + (size_t)t * Ee;
    int i1 = 0; float v1 = r[0];
    for (int e = 1; e < Ee; e++) if (r[e] > v1) { v1 = r[e]; i1 = e; }
    int i2 = -1; float v2 = -3.4e38f;
    for (int e = 0; e < Ee; e++) { if (e == i1) continue; if (r[e] > v2) { v2 = r[e]; i2 = e; } }
    float e1 = 1.f, e2 = __expf(v2 - v1);
    float inv = 1.f / (e1 + e2);
    g_sel[t * 2] = i1; g_sel[t * 2 + 1] = i2;
    g_rw[t * 2] = e1 * inv; g_rw[t * 2 + 1] = e2 * inv;
    int s1 = atomicAdd(&g_cnt[i1], 1); g_bucket[i1 * NPAIR + s1] = t * 2;
    int s2 = atomicAdd(&g_cnt[i2], 1); g_bucket[i2 * NPAIR + s2] = t * 2 + 1;
}

// ---------------- scatter + combine ----------------
__global__ void feo_scatter(float* __restrict__ FEO) {
    int p = blockIdx.x;
    int t = p >> 1, e = g_sel[p];
    float* dst = FEO + ((size_t)t * Ee + e) * Cc;
    const float* src = g_po + (size_t)p * Cc;
    for (int c = threadIdx.x; c < Cc; c += 128) dst[c] = src[c];
}

__global__ void moe_combine() {
    int t = blockIdx.x;
    float w0 = g_rw[t * 2], w1r = g_rw[t * 2 + 1];
    float* hrow = g_h + (size_t)t * Cc;
    const float* p0 = g_po + (size_t)(t * 2) * Cc;
    const float* p1 = g_po + (size_t)(t * 2 + 1) * Cc;
    for (int c = threadIdx.x; c < Cc; c += 128)
        hrow[c] += w0 * p0[c] + w1r * p1[c];
}

// ---------------- launch ----------------
extern "C" void kernel_launch(void* const* d_in, const int* in_sizes, int n_in,
                              void* d_out, int out_size) {
    const int*   ids  = (const int*)d_in[0];
    const float* emb  = (const float*)d_in[1];
    const float* wq   = (const float*)d_in[2];
    const float* wk   = (const float*)d_in[3];
    const float* wv   = (const float*)d_in[4];
    const float* wo   = (const float*)d_in[5];
    const float* gate = (const float*)d_in[6];
    const float* w1   = (const float*)d_in[7];
    const float* w2   = (const float*)d_in[8];
    const float* g1   = (const float*)d_in[9];
    const float* b1   = (const float*)d_in[10];
    const float* g2   = (const float*)d_in[11];
    const float* b2   = (const float*)d_in[12];
    const float* lm   = (const float*)d_in[13];
    float* out = (float*)d_out;

    float *p_h, *p_x, *p_q, *p_k, *p_v, *p_ao, *p_x2, *p_rl, *p_hid;
    cudaGetSymbolAddress((void**)&p_h,  g_h);
    cudaGetSymbolAddress((void**)&p_x,  g_x);
    cudaGetSymbolAddress((void**)&p_q,  g_q);
    cudaGetSymbolAddress((void**)&p_k,  g_k);
    cudaGetSymbolAddress((void**)&p_v,  g_v);
    cudaGetSymbolAddress((void**)&p_ao, g_ao);
    cudaGetSymbolAddress((void**)&p_x2, g_x2);
    cudaGetSymbolAddress((void**)&p_rl, g_rl);
    cudaGetSymbolAddress((void**)&p_hid, g_hid);

    cudaFuncSetAttribute((const void*)mma_gemm<1,0>, cudaFuncAttributeMaxDynamicSharedMemorySize,
                         GEMM_SMEM_BYTES);
    cudaFuncSetAttribute((const void*)mma_gemm<0,1>, cudaFuncAttributeMaxDynamicSharedMemorySize,
                         GEMM_SMEM_BYTES);
    cudaFuncSetAttribute((const void*)moe_mma<0>, cudaFuncAttributeMaxDynamicSharedMemorySize,
                         MOE_SMEM_BYTES);
    cudaFuncSetAttribute((const void*)fattn_kernel, cudaFuncAttributeMaxDynamicSharedMemorySize,
                         FA_SMEM);

    const size_t L_LOG = (size_t)NTOK * Vv;
    const size_t L_FEO = (size_t)NTOK * Ee * Cc;
    const size_t L_RL  = (size_t)NTOK * Ee;
    const size_t L_X2  = (size_t)NTOK * Cc;
    const size_t OFF_FEO = L_LOG;
    const size_t OFF_RL  = OFF_FEO + L_FEO;
    const size_t OFF_X2  = OFF_RL + L_RL;
    bool full = (size_t)out_size >= OFF_X2 + L_X2;

    embed_kernel<<<NTOK, 128>>>(ids, emb, p_h);
    ln_kernel<<<NTOK, 128>>>(p_h, g1, b1, p_x);

    mma_gemm<1,0><<<dim3(Cc / 128, NTOK / 128, 3), 256, GEMM_SMEM_BYTES>>>(
        p_x, wq, wk, wv, nullptr, p_q, p_k, p_v, NTOK, Cc, Cc);

    fattn_kernel<<<dim3(Tt / 64, Bsz * Hh), 128, FA_SMEM>>>(p_q, p_k, p_v, p_ao);

    mma_gemm<1,0><<<dim3(Cc / 128, NTOK / 128, 1), 256, GEMM_SMEM_BYTES>>>(
        p_ao, wo, wo, wo, p_h, p_h, p_h, p_h, NTOK, Cc, Cc);

    ln_kernel<<<NTOK, 128>>>(p_h, g2, b2, p_x2);

    gemm_kernel<<<dim3(1, NTOK / 64), 128>>>(p_x2, gate, nullptr, p_rl, NTOK, Ee, Cc);

    zero_cnt_kernel<<<1, 32>>>();
    topk_kernel<<<NTOK / 128, 128>>>(p_rl);

    // MoE single-pass tf32 (FEO error budget ~4e-4 < 1e-3)
    moe_mma<0><<<dim3(Ii / 128, NPAIR / MOE_M, Ee), 256, MOE_SMEM_BYTES>>>(
        p_x2, w1, Cc, Ii, 1);
    moe_mma<0><<<dim3(Cc / 128, NPAIR / MOE_M, Ee), 256, MOE_SMEM_BYTES>>>(
        p_hid, w2, Ii, Cc, 2);

    if (full) {
        cudaMemsetAsync(out + OFF_FEO, 0, L_FEO * sizeof(float));
        feo_scatter<<<NPAIR, 128>>>(out + OFF_FEO);
    }
    moe_combine<<<NTOK, 128>>>();

    // lm_head: single-pass tf32, SWAP=1 so consecutive blocks share B strips
    mma_gemm<0,1><<<dim3(NTOK / 128, Vv / 128, 1), 256, GEMM_SMEM_BYTES>>>(
        p_h, lm, lm, lm, nullptr, out, out, out, NTOK, Vv, Cc);

    if (full) {
        cudaMemcpyAsync(out + OFF_RL, p_rl, L_RL * sizeof(float), cudaMemcpyDeviceToDevice);
        cudaMemcpyAsync(out + OFF_X2, p_x2, L_X2 * sizeof(float), cudaMemcpyDeviceToDevice);
    }
}